// round 9
// baseline (speedup 1.0000x reference)
#include <cuda_runtime.h>
#include <math.h>
#include <stdint.h>

#define HID   768
#define NH    12
#define DH    64
#define BATCH 4
#define SEQ   2048
#define MTOT  (BATCH*SEQ)   // 8192

// Scratch (allocation-free rule: __device__ globals)
__device__ float g_hsr[MTOT*HID];        // hs rounded to tf32
__device__ float g_wr[4][HID*HID];       // Wq,Wk,Wv,Wo rounded
__device__ float g_qh[MTOT*HID];         // q head-major rounded
__device__ float g_kh[MTOT*HID];
__device__ float g_vh[MTOT*HID];
__device__ float g_ctx[MTOT*HID];        // ctx standard layout, rounded

// ---------------------------------------------------------------------------
__device__ __forceinline__ uint32_t f2tf(float x) {
    uint32_t r;
    asm("cvt.rna.tf32.f32 %0, %1;" : "=r"(r) : "f"(x));
    return r;
}
__device__ __forceinline__ float f2tf_f(float x) {
    uint32_t u = f2tf(x); return __uint_as_float(u);
}
__device__ __forceinline__ float fexp2(float x) {
    float y;
    asm("ex2.approx.f32 %0, %1;" : "=f"(y) : "f"(x));
    return y;
}

__device__ __forceinline__ void mma_tf32(float c[4],
    uint32_t a0, uint32_t a1, uint32_t a2, uint32_t a3,
    uint32_t b0, uint32_t b1)
{
    asm volatile(
        "mma.sync.aligned.m16n8k8.row.col.f32.tf32.tf32.f32 "
        "{%0,%1,%2,%3}, {%4,%5,%6,%7}, {%8,%9}, {%0,%1,%2,%3};"
        : "+f"(c[0]), "+f"(c[1]), "+f"(c[2]), "+f"(c[3])
        : "r"(a0), "r"(a1), "r"(a2), "r"(a3), "r"(b0), "r"(b1));
}

__device__ __forceinline__ uint32_t smaddr(const void* p) {
    return (uint32_t)__cvta_generic_to_shared(p);
}
__device__ __forceinline__ void cpa16(uint32_t dst, const void* src) {
    asm volatile("cp.async.cg.shared.global [%0], [%1], 16;" :: "r"(dst), "l"(src));
}
__device__ __forceinline__ void cpa_commit() {
    asm volatile("cp.async.commit_group;" ::: "memory");
}
__device__ __forceinline__ void cpa_wait1() {
    asm volatile("cp.async.wait_group 1;" ::: "memory");
}

// ---------------------------------------------------------------------------
// Pre-round kernels
// ---------------------------------------------------------------------------
__global__ void round_hs(const float* __restrict__ in, float* __restrict__ out, int n4)
{
    int i = blockIdx.x * blockDim.x + threadIdx.x;
    if (i < n4) {
        float4 v = ((const float4*)in)[i];
        ((float4*)out)[i] = make_float4(f2tf_f(v.x), f2tf_f(v.y), f2tf_f(v.z), f2tf_f(v.w));
    }
}
__global__ void round_w4(const float* __restrict__ w0, const float* __restrict__ w1,
                         const float* __restrict__ w2, const float* __restrict__ w3,
                         float* __restrict__ out)
{
    const int wi = blockIdx.y;
    const float* src = wi == 0 ? w0 : (wi == 1 ? w1 : (wi == 2 ? w2 : w3));
    float* dst = out + (size_t)wi * HID * HID;
    int i = blockIdx.x * blockDim.x + threadIdx.x;
    if (i < HID * HID / 4) {
        float4 v = ((const float4*)src)[i];
        ((float4*)dst)[i] = make_float4(f2tf_f(v.x), f2tf_f(v.y), f2tf_f(v.z), f2tf_f(v.w));
    }
}

// ---------------------------------------------------------------------------
// GEMM body: C = A[M,768] @ W[768,768] + bias. Inputs pre-rounded tf32.
// BM=256, BN=128, BK=32. 256 thr / 8 warps (4m x 2n), warp tile 64x64.
// cp.async 2-stage. Smem: As[2][256][36] + Bs[2][32][136] = 108544 B, 1 CTA/SM.
// ---------------------------------------------------------------------------
#define G_AS (256*36)
#define G_BS (32*136)
#define G_SMEM_BYTES ((2*G_AS + 2*G_BS)*4)

template<bool GELU, bool HEADM>
__device__ __forceinline__ void gemm_body(
    const float* __restrict__ A, const float* __restrict__ W,
    const float* __restrict__ bias, float* __restrict__ C)
{
    extern __shared__ float sg[];
    float* Asm = sg;                 // [2][256][36]
    float* Bsm = sg + 2 * G_AS;      // [2][32][136]

    const int tid  = threadIdx.x;
    const int lane = tid & 31;
    const int warp = tid >> 5;
    const int wm   = (warp >> 1) * 64;
    const int wn   = (warp & 1) * 64;
    const int m0   = blockIdx.y * 256;
    const int n0   = blockIdx.x * 128;
    const int c_   = lane & 3;
    const int q_   = lane >> 2;

    const int ar = tid >> 3, ac = (tid & 7) * 4;     // A: 8 chunks, rows +32
    const int br = tid >> 5, bc = (tid & 31) * 4;    // B: 4 chunks, rows +8

    float acc[4][8][4] = {};
    const int nT = HID / 32;   // 24

    // prologue: tile 0 -> buf 0
    {
        #pragma unroll
        for (int i = 0; i < 8; i++) {
            int row = ar + i * 32;
            cpa16(smaddr(&Asm[row * 36 + ac]), &A[(size_t)(m0 + row) * HID + ac]);
        }
        #pragma unroll
        for (int i = 0; i < 4; i++) {
            int row = br + i * 8;
            cpa16(smaddr(&Bsm[row * 136 + bc]), &W[(size_t)row * HID + n0 + bc]);
        }
        cpa_commit();
    }

    for (int t = 0; t < nT; t++) {
        const int cur = t & 1;
        if (t + 1 < nT) {
            const int k0 = (t + 1) * 32;
            float* Ad = Asm + (cur ^ 1) * G_AS;
            float* Bd = Bsm + (cur ^ 1) * G_BS;
            #pragma unroll
            for (int i = 0; i < 8; i++) {
                int row = ar + i * 32;
                cpa16(smaddr(&Ad[row * 36 + ac]), &A[(size_t)(m0 + row) * HID + k0 + ac]);
            }
            #pragma unroll
            for (int i = 0; i < 4; i++) {
                int row = br + i * 8;
                cpa16(smaddr(&Bd[row * 136 + bc]), &W[(size_t)(k0 + row) * HID + n0 + bc]);
            }
        }
        cpa_commit();
        cpa_wait1();
        __syncthreads();

        const float* Ac = Asm + cur * G_AS;
        const float* Bc = Bsm + cur * G_BS;
        #pragma unroll
        for (int ksi = 0; ksi < 4; ksi++) {
            uint32_t a[4][4];
            #pragma unroll
            for (int mt = 0; mt < 4; mt++) {
                int r = wm + mt * 16 + q_;
                a[mt][0] = __float_as_uint(Ac[r * 36 + ksi * 8 + c_]);
                a[mt][1] = __float_as_uint(Ac[(r + 8) * 36 + ksi * 8 + c_]);
                a[mt][2] = __float_as_uint(Ac[r * 36 + ksi * 8 + c_ + 4]);
                a[mt][3] = __float_as_uint(Ac[(r + 8) * 36 + ksi * 8 + c_ + 4]);
            }
            #pragma unroll
            for (int nt = 0; nt < 8; nt++) {
                uint32_t b0 = __float_as_uint(Bc[(ksi * 8 + c_) * 136 + wn + nt * 8 + q_]);
                uint32_t b1 = __float_as_uint(Bc[(ksi * 8 + c_ + 4) * 136 + wn + nt * 8 + q_]);
                #pragma unroll
                for (int mt = 0; mt < 4; mt++)
                    mma_tf32(acc[mt][nt], a[mt][0], a[mt][1], a[mt][2], a[mt][3], b0, b1);
            }
        }
        __syncthreads();
    }

    // epilogue
    #pragma unroll
    for (int mt = 0; mt < 4; mt++) {
        int r0 = m0 + wm + mt * 16 + q_;
        #pragma unroll
        for (int nt = 0; nt < 8; nt++) {
            int col = n0 + wn + nt * 8 + 2 * c_;
            float bv0 = bias[col], bv1 = bias[col + 1];
            float v0 = acc[mt][nt][0] + bv0;
            float v1 = acc[mt][nt][1] + bv1;
            float v2 = acc[mt][nt][2] + bv0;
            float v3 = acc[mt][nt][3] + bv1;
            if (GELU) {
                v0 *= normcdff(v0); v1 *= normcdff(v1);
                v2 *= normcdff(v2); v3 *= normcdff(v3);
                *(float2*)&C[(size_t)r0       * HID + col] = make_float2(v0, v1);
                *(float2*)&C[(size_t)(r0 + 8) * HID + col] = make_float2(v2, v3);
            } else if (HEADM) {
                int h = col >> 6, d = col & 63;
                int b0r = r0 >> 11, s0 = r0 & 2047;
                size_t dst0 = ((size_t)(b0r * NH + h) * SEQ + s0) * 64 + d;
                size_t dst1 = dst0 + 8 * 64;
                *(float2*)&C[dst0] = make_float2(f2tf_f(v0), f2tf_f(v1));
                *(float2*)&C[dst1] = make_float2(f2tf_f(v2), f2tf_f(v3));
            } else {
                *(float2*)&C[(size_t)r0       * HID + col] = make_float2(f2tf_f(v0), f2tf_f(v1));
                *(float2*)&C[(size_t)(r0 + 8) * HID + col] = make_float2(f2tf_f(v2), f2tf_f(v3));
            }
        }
    }
}

template<bool GELU, bool HEADM>
__global__ __launch_bounds__(256, 1) void gemm6(
    const float* __restrict__ A, const float* __restrict__ W,
    const float* __restrict__ bias, float* __restrict__ C)
{
    gemm_body<GELU, HEADM>(A, W, bias, C);
}

__global__ __launch_bounds__(256, 1) void gemm6_qkv(
    const float* __restrict__ A, const float* __restrict__ Wr,
    const float* __restrict__ b0, const float* __restrict__ b1, const float* __restrict__ b2,
    float* __restrict__ C0, float* __restrict__ C1, float* __restrict__ C2)
{
    const int z = blockIdx.z;
    const float* W = Wr + (size_t)z * HID * HID;
    const float* bb = z == 0 ? b0 : (z == 1 ? b1 : b2);
    float* C = z == 0 ? C0 : (z == 1 ? C1 : C2);
    gemm_body<false, true>(A, W, bb, C);
}

// ---------------------------------------------------------------------------
// Flash attention, unnormalized streaming softmax.
// Block = (b, h, 128-q-tile), 128 thr / 4 warps, warp = 32 q-rows, 2 CTA/SM.
// NEW: softmax/PV split into two column-halves; even warps do half0->half1,
// odd warps do half1->half0, so MUFU (exp) on one warp overlaps tensor (PV)
// on its SMSP partner instead of phase-locking.
// Smem: Ps[128][68] + K[2][64][68] + V[2][64][72] + ms[2][64] = 107008 B.
// ---------------------------------------------------------------------------
#define A_KS (64*68)
#define A_VS (64*72)
#define A_P_OFF 0
#define A_K_OFF (128*68)
#define A_V_OFF (A_K_OFF + 2*A_KS)
#define A_M_OFF (A_V_OFF + 2*A_VS)
#define A_SMEM_BYTES ((A_M_OFF + 128)*4)

#define SOFTMAX_PV_HALF(H)                                                    \
do {                                                                          \
    _Pragma("unroll")                                                         \
    for (int mt = 0; mt < 2; mt++) {                                          \
        _Pragma("unroll")                                                     \
        for (int nt = (H)*4; nt < (H)*4 + 4; nt++) {                          \
            float mk0 = mc[nt * 8 + 2 * c_];                                  \
            float mk1 = mc[nt * 8 + 2 * c_ + 1];                              \
            float e;                                                          \
            e = mq[mt][0] * mk0; s[mt][nt][0] = fexp2(e * (s[mt][nt][0] * scale2) - (1.0f - e) * pen2); \
            e = mq[mt][0] * mk1; s[mt][nt][1] = fexp2(e * (s[mt][nt][1] * scale2) - (1.0f - e) * pen2); \
            e = mq[mt][1] * mk0; s[mt][nt][2] = fexp2(e * (s[mt][nt][2] * scale2) - (1.0f - e) * pen2); \
            e = mq[mt][1] * mk1; s[mt][nt][3] = fexp2(e * (s[mt][nt][3] * scale2) - (1.0f - e) * pen2); \
            l[mt][0] += s[mt][nt][0] + s[mt][nt][1];                          \
            l[mt][1] += s[mt][nt][2] + s[mt][nt][3];                          \
        }                                                                     \
    }                                                                         \
    _Pragma("unroll")                                                         \
    for (int mt = 0; mt < 2; mt++) {                                          \
        int rr = wq + mt * 16 + q_;                                           \
        _Pragma("unroll")                                                     \
        for (int nt = (H)*4; nt < (H)*4 + 4; nt++) {                          \
            *(uint2*)&Ps[rr * 68 + nt * 8 + 2 * c_] =                         \
                make_uint2(f2tf(s[mt][nt][0]), f2tf(s[mt][nt][1]));           \
            *(uint2*)&Ps[(rr + 8) * 68 + nt * 8 + 2 * c_] =                   \
                make_uint2(f2tf(s[mt][nt][2]), f2tf(s[mt][nt][3]));           \
        }                                                                     \
    }                                                                         \
    __syncwarp();                                                             \
    _Pragma("unroll")                                                         \
    for (int ksi = (H)*4; ksi < (H)*4 + 4; ksi++) {                           \
        uint32_t a[2][4];                                                     \
        _Pragma("unroll")                                                     \
        for (int mt = 0; mt < 2; mt++) {                                      \
            int rr = wq + mt * 16 + q_;                                       \
            a[mt][0] = __float_as_uint(Ps[rr * 68 + ksi * 8 + c_]);           \
            a[mt][1] = __float_as_uint(Ps[(rr + 8) * 68 + ksi * 8 + c_]);     \
            a[mt][2] = __float_as_uint(Ps[rr * 68 + ksi * 8 + c_ + 4]);       \
            a[mt][3] = __float_as_uint(Ps[(rr + 8) * 68 + ksi * 8 + c_ + 4]); \
        }                                                                     \
        _Pragma("unroll")                                                     \
        for (int nt = 0; nt < 8; nt++) {                                      \
            uint32_t b0 = __float_as_uint(Vc[(ksi * 8 + c_) * 72 + nt * 8 + q_]);     \
            uint32_t b1 = __float_as_uint(Vc[(ksi * 8 + c_ + 4) * 72 + nt * 8 + q_]); \
            mma_tf32(o[0][nt], a[0][0], a[0][1], a[0][2], a[0][3], b0, b1);   \
            mma_tf32(o[1][nt], a[1][0], a[1][1], a[1][2], a[1][3], b0, b1);   \
        }                                                                     \
    }                                                                         \
} while (0)

__global__ __launch_bounds__(128, 2) void attn6(
    const float* __restrict__ qh, const float* __restrict__ kh,
    const float* __restrict__ vh, const float* __restrict__ mask,
    float* __restrict__ ctx)
{
    extern __shared__ float sa[];
    float* Ps   = sa + A_P_OFF;
    float* Kbuf = sa + A_K_OFF;
    float* Vbuf = sa + A_V_OFF;
    float* msb  = sa + A_M_OFF;

    const int tid  = threadIdx.x;
    const int lane = tid & 31;
    const int warp = tid >> 5;
    const int c_   = lane & 3;
    const int q_   = lane >> 2;
    const int b    = blockIdx.z;
    const int h    = blockIdx.y;
    const int q0   = blockIdx.x * 128;
    const int bS   = b * SEQ;
    const int bh   = b * NH + h;
    const int wq   = warp * 32;
    const float scale2 = 0.125f * 1.44269504f;
    const float pen2   = 1e9f * 1.44269504f;

    const int prow = tid >> 4;
    const int pch  = (tid & 15) * 4;

    const float* kbase0 = &kh[(size_t)bh * SEQ * 64];
    const float* vbase0 = &vh[(size_t)bh * SEQ * 64];

    {
        #pragma unroll
        for (int i = 0; i < 8; i++) {
            int row = prow + i * 8;
            cpa16(smaddr(&Kbuf[row * 68 + pch]), kbase0 + (size_t)row * 64 + pch);
            cpa16(smaddr(&Vbuf[row * 72 + pch]), vbase0 + (size_t)row * 64 + pch);
        }
        if (tid < 16) cpa16(smaddr(&msb[tid * 4]), &mask[bS + tid * 4]);
        cpa_commit();
    }

    uint32_t qa[2][8][4];
    #pragma unroll
    for (int mt = 0; mt < 2; mt++) {
        const float* p0 = &qh[((size_t)bh * SEQ + q0 + wq + mt * 16 + q_) * 64];
        const float* p1 = p0 + 8 * 64;
        #pragma unroll
        for (int ksi = 0; ksi < 8; ksi++) {
            qa[mt][ksi][0] = __float_as_uint(p0[ksi * 8 + c_]);
            qa[mt][ksi][1] = __float_as_uint(p1[ksi * 8 + c_]);
            qa[mt][ksi][2] = __float_as_uint(p0[ksi * 8 + c_ + 4]);
            qa[mt][ksi][3] = __float_as_uint(p1[ksi * 8 + c_ + 4]);
        }
    }

    float mq[2][2];
    #pragma unroll
    for (int mt = 0; mt < 2; mt++) {
        mq[mt][0] = mask[bS + q0 + wq + mt * 16 + q_];
        mq[mt][1] = mask[bS + q0 + wq + mt * 16 + q_ + 8];
    }

    float l[2][2] = {};
    float o[2][8][4] = {};

    const int nT = SEQ / 64;
    for (int t = 0; t < nT; t++) {
        const int cur = t & 1;
        if (t + 1 < nT) {
            const int k0 = (t + 1) * 64;
            float* Kd = Kbuf + (cur ^ 1) * A_KS;
            float* Vd = Vbuf + (cur ^ 1) * A_VS;
            const float* kb = kbase0 + (size_t)k0 * 64;
            const float* vb = vbase0 + (size_t)k0 * 64;
            #pragma unroll
            for (int i = 0; i < 8; i++) {
                int row = prow + i * 8;
                cpa16(smaddr(&Kd[row * 68 + pch]), kb + (size_t)row * 64 + pch);
                cpa16(smaddr(&Vd[row * 72 + pch]), vb + (size_t)row * 64 + pch);
            }
            if (tid < 16) cpa16(smaddr(&msb[(cur ^ 1) * 64 + tid * 4]), &mask[bS + k0 + tid * 4]);
        }
        cpa_commit();
        cpa_wait1();
        __syncthreads();

        float* Kc = Kbuf + cur * A_KS;
        float* Vc = Vbuf + cur * A_VS;
        const float* mc = msb + cur * 64;

        // ---- S = Q K^T (warp: 32x64)
        float s[2][8][4] = {};
        #pragma unroll
        for (int ksi = 0; ksi < 8; ksi++) {
            #pragma unroll
            for (int nt = 0; nt < 8; nt++) {
                uint32_t b0 = __float_as_uint(Kc[(nt * 8 + q_) * 68 + ksi * 8 + c_]);
                uint32_t b1 = __float_as_uint(Kc[(nt * 8 + q_) * 68 + ksi * 8 + c_ + 4]);
                mma_tf32(s[0][nt], qa[0][ksi][0], qa[0][ksi][1], qa[0][ksi][2], qa[0][ksi][3], b0, b1);
                mma_tf32(s[1][nt], qa[1][ksi][0], qa[1][ksi][1], qa[1][ksi][2], qa[1][ksi][3], b0, b1);
            }
        }

        // ---- staggered softmax + PV: even warps 0->1, odd warps 1->0
        if (warp & 1) {
            SOFTMAX_PV_HALF(1);
            SOFTMAX_PV_HALF(0);
        } else {
            SOFTMAX_PV_HALF(0);
            SOFTMAX_PV_HALF(1);
        }
        __syncthreads();   // protect Kc/Vc/mc before next prefetch overwrites
    }

    #pragma unroll
    for (int mt = 0; mt < 2; mt++) {
        #pragma unroll
        for (int half = 0; half < 2; half++) {
            l[mt][half] += __shfl_xor_sync(0xffffffffu, l[mt][half], 1);
            l[mt][half] += __shfl_xor_sync(0xffffffffu, l[mt][half], 2);
        }
    }

    #pragma unroll
    for (int mt = 0; mt < 2; mt++) {
        float inv0 = 1.0f / l[mt][0], inv1 = 1.0f / l[mt][1];
        int gr = bS + q0 + wq + mt * 16 + q_;
        #pragma unroll
        for (int nt = 0; nt < 8; nt++) {
            int col = h * DH + nt * 8 + 2 * c_;
            *(float2*)&ctx[(size_t)gr * HID + col] =
                make_float2(f2tf_f(o[mt][nt][0] * inv0), f2tf_f(o[mt][nt][1] * inv0));
            *(float2*)&ctx[(size_t)(gr + 8) * HID + col] =
                make_float2(f2tf_f(o[mt][nt][2] * inv1), f2tf_f(o[mt][nt][3] * inv1));
        }
    }
}

// ---------------------------------------------------------------------------
extern "C" void kernel_launch(void* const* d_in, const int* in_sizes, int n_in,
                              void* d_out, int out_size)
{
    const float* hs   = (const float*)d_in[0];
    const float* mask = (const float*)d_in[1];
    const float* Wq   = (const float*)d_in[2];
    const float* bq   = (const float*)d_in[3];
    const float* Wk   = (const float*)d_in[4];
    const float* bk   = (const float*)d_in[5];
    const float* Wv   = (const float*)d_in[6];
    const float* bv   = (const float*)d_in[7];
    const float* Wo   = (const float*)d_in[8];
    const float* bo   = (const float*)d_in[9];
    float* out = (float*)d_out;

    float *hsr, *wr, *qh, *kh, *vh, *cb;
    cudaGetSymbolAddress((void**)&hsr, g_hsr);
    cudaGetSymbolAddress((void**)&wr,  g_wr);
    cudaGetSymbolAddress((void**)&qh,  g_qh);
    cudaGetSymbolAddress((void**)&kh,  g_kh);
    cudaGetSymbolAddress((void**)&vh,  g_vh);
    cudaGetSymbolAddress((void**)&cb,  g_ctx);

    cudaFuncSetAttribute(gemm6_qkv,          cudaFuncAttributeMaxDynamicSharedMemorySize, G_SMEM_BYTES);
    cudaFuncSetAttribute(gemm6<true,false>,  cudaFuncAttributeMaxDynamicSharedMemorySize, G_SMEM_BYTES);
    cudaFuncSetAttribute(attn6,              cudaFuncAttributeMaxDynamicSharedMemorySize, A_SMEM_BYTES);

    // --- pre-round inputs to tf32 ---
    round_hs<<<(MTOT * HID / 4 + 255) / 256, 256>>>(hs, hsr, MTOT * HID / 4);
    dim3 wgrid((HID * HID / 4 + 255) / 256, 4);
    round_w4<<<wgrid, 256>>>(Wq, Wk, Wv, Wo, wr);

    // --- fused QKV projections (write head-major rounded) ---
    dim3 qkvgrid(HID / 128, MTOT / 256, 3);   // (6, 32, 3)
    gemm6_qkv<<<qkvgrid, 256, G_SMEM_BYTES>>>(
        hsr, wr, bq, bk, bv, qh, kh, vh);

    // --- attention ---
    dim3 agrid(SEQ / 128, NH, BATCH);    // (16, 12, 4) = 768 blocks
    attn6<<<agrid, 128, A_SMEM_BYTES>>>(qh, kh, vh, mask, cb);

    // --- output projection + GELU ---
    dim3 ggrid(HID / 128, MTOT / 256);   // (6, 32)
    gemm6<true,false><<<ggrid, 256, G_SMEM_BYTES>>>(cb, wr + 3 * (size_t)HID * HID, bo, out);
}

// round 10
// speedup vs baseline: 1.1465x; 1.1465x over previous
#include <cuda_runtime.h>
#include <math.h>
#include <stdint.h>

#define HID   768
#define NH    12
#define DH    64
#define BATCH 4
#define SEQ   2048
#define MTOT  (BATCH*SEQ)   // 8192

// Scratch (allocation-free rule: __device__ globals)
__device__ float g_hsr[MTOT*HID];        // hs rounded to tf32
__device__ float g_wr[4][HID*HID];       // Wq,Wk,Wv,Wo rounded
__device__ float g_qh[MTOT*HID];         // q head-major rounded
__device__ float g_kh[MTOT*HID];
__device__ float g_vh[MTOT*HID];
__device__ float g_ctx[MTOT*HID];        // ctx standard layout, rounded

// ---------------------------------------------------------------------------
__device__ __forceinline__ uint32_t f2tf(float x) {
    uint32_t r;
    asm("cvt.rna.tf32.f32 %0, %1;" : "=r"(r) : "f"(x));
    return r;
}
__device__ __forceinline__ float f2tf_f(float x) {
    uint32_t u = f2tf(x); return __uint_as_float(u);
}
__device__ __forceinline__ float fexp2(float x) {
    float y;
    asm("ex2.approx.f32 %0, %1;" : "=f"(y) : "f"(x));
    return y;
}

__device__ __forceinline__ void mma_tf32(float c[4],
    uint32_t a0, uint32_t a1, uint32_t a2, uint32_t a3,
    uint32_t b0, uint32_t b1)
{
    asm volatile(
        "mma.sync.aligned.m16n8k8.row.col.f32.tf32.tf32.f32 "
        "{%0,%1,%2,%3}, {%4,%5,%6,%7}, {%8,%9}, {%0,%1,%2,%3};"
        : "+f"(c[0]), "+f"(c[1]), "+f"(c[2]), "+f"(c[3])
        : "r"(a0), "r"(a1), "r"(a2), "r"(a3), "r"(b0), "r"(b1));
}

__device__ __forceinline__ uint32_t smaddr(const void* p) {
    return (uint32_t)__cvta_generic_to_shared(p);
}
__device__ __forceinline__ void cpa16(uint32_t dst, const void* src) {
    asm volatile("cp.async.cg.shared.global [%0], [%1], 16;" :: "r"(dst), "l"(src));
}
__device__ __forceinline__ void cpa_commit() {
    asm volatile("cp.async.commit_group;" ::: "memory");
}
__device__ __forceinline__ void cpa_wait1() {
    asm volatile("cp.async.wait_group 1;" ::: "memory");
}

// ---------------------------------------------------------------------------
// Pre-round kernels
// ---------------------------------------------------------------------------
__global__ void round_hs(const float* __restrict__ in, float* __restrict__ out, int n4)
{
    int i = blockIdx.x * blockDim.x + threadIdx.x;
    if (i < n4) {
        float4 v = ((const float4*)in)[i];
        ((float4*)out)[i] = make_float4(f2tf_f(v.x), f2tf_f(v.y), f2tf_f(v.z), f2tf_f(v.w));
    }
}
__global__ void round_w4(const float* __restrict__ w0, const float* __restrict__ w1,
                         const float* __restrict__ w2, const float* __restrict__ w3,
                         float* __restrict__ out)
{
    const int wi = blockIdx.y;
    const float* src = wi == 0 ? w0 : (wi == 1 ? w1 : (wi == 2 ? w2 : w3));
    float* dst = out + (size_t)wi * HID * HID;
    int i = blockIdx.x * blockDim.x + threadIdx.x;
    if (i < HID * HID / 4) {
        float4 v = ((const float4*)src)[i];
        ((float4*)dst)[i] = make_float4(f2tf_f(v.x), f2tf_f(v.y), f2tf_f(v.z), f2tf_f(v.w));
    }
}

// ---------------------------------------------------------------------------
// GEMM body: C = A[M,768] @ W[768,768] + bias. Inputs pre-rounded tf32.
// BM=128, BN=128, BK=32. 256 thr / 8 warps (4m x 2n), warp tile 32x64.
// 2 CTA/SM -> 16 warps/SM (4/SMSP) for latency hiding.
// cp.async 2-stage. Smem: As[2][128][36] + Bs[2][32][136] = 71680 B.
// ---------------------------------------------------------------------------
#define G_AS (128*36)
#define G_BS (32*136)
#define G_SMEM_BYTES ((2*G_AS + 2*G_BS)*4)

template<bool GELU, bool HEADM>
__device__ __forceinline__ void gemm_body(
    const float* __restrict__ A, const float* __restrict__ W,
    const float* __restrict__ bias, float* __restrict__ C)
{
    extern __shared__ float sg[];
    float* Asm = sg;                 // [2][128][36]
    float* Bsm = sg + 2 * G_AS;      // [2][32][136]

    const int tid  = threadIdx.x;
    const int lane = tid & 31;
    const int warp = tid >> 5;
    const int wm   = (warp >> 1) * 32;
    const int wn   = (warp & 1) * 64;
    const int m0   = blockIdx.y * 128;
    const int n0   = blockIdx.x * 128;
    const int c_   = lane & 3;
    const int q_   = lane >> 2;

    const int ar = tid >> 3, ac = (tid & 7) * 4;     // A: 4 chunks, rows +32
    const int br = tid >> 5, bc = (tid & 31) * 4;    // B: 4 chunks, rows +8

    float acc[2][8][4] = {};
    const int nT = HID / 32;   // 24

    // prologue: tile 0 -> buf 0
    {
        #pragma unroll
        for (int i = 0; i < 4; i++) {
            int row = ar + i * 32;
            cpa16(smaddr(&Asm[row * 36 + ac]), &A[(size_t)(m0 + row) * HID + ac]);
        }
        #pragma unroll
        for (int i = 0; i < 4; i++) {
            int row = br + i * 8;
            cpa16(smaddr(&Bsm[row * 136 + bc]), &W[(size_t)row * HID + n0 + bc]);
        }
        cpa_commit();
    }

    for (int t = 0; t < nT; t++) {
        const int cur = t & 1;
        if (t + 1 < nT) {
            const int k0 = (t + 1) * 32;
            float* Ad = Asm + (cur ^ 1) * G_AS;
            float* Bd = Bsm + (cur ^ 1) * G_BS;
            #pragma unroll
            for (int i = 0; i < 4; i++) {
                int row = ar + i * 32;
                cpa16(smaddr(&Ad[row * 36 + ac]), &A[(size_t)(m0 + row) * HID + k0 + ac]);
            }
            #pragma unroll
            for (int i = 0; i < 4; i++) {
                int row = br + i * 8;
                cpa16(smaddr(&Bd[row * 136 + bc]), &W[(size_t)(k0 + row) * HID + n0 + bc]);
            }
        }
        cpa_commit();
        cpa_wait1();
        __syncthreads();

        const float* Ac = Asm + cur * G_AS;
        const float* Bc = Bsm + cur * G_BS;
        #pragma unroll
        for (int ksi = 0; ksi < 4; ksi++) {
            uint32_t a[2][4];
            #pragma unroll
            for (int mt = 0; mt < 2; mt++) {
                int r = wm + mt * 16 + q_;
                a[mt][0] = __float_as_uint(Ac[r * 36 + ksi * 8 + c_]);
                a[mt][1] = __float_as_uint(Ac[(r + 8) * 36 + ksi * 8 + c_]);
                a[mt][2] = __float_as_uint(Ac[r * 36 + ksi * 8 + c_ + 4]);
                a[mt][3] = __float_as_uint(Ac[(r + 8) * 36 + ksi * 8 + c_ + 4]);
            }
            #pragma unroll
            for (int nt = 0; nt < 8; nt++) {
                uint32_t b0 = __float_as_uint(Bc[(ksi * 8 + c_) * 136 + wn + nt * 8 + q_]);
                uint32_t b1 = __float_as_uint(Bc[(ksi * 8 + c_ + 4) * 136 + wn + nt * 8 + q_]);
                mma_tf32(acc[0][nt], a[0][0], a[0][1], a[0][2], a[0][3], b0, b1);
                mma_tf32(acc[1][nt], a[1][0], a[1][1], a[1][2], a[1][3], b0, b1);
            }
        }
        __syncthreads();
    }

    // epilogue
    #pragma unroll
    for (int mt = 0; mt < 2; mt++) {
        int r0 = m0 + wm + mt * 16 + q_;
        #pragma unroll
        for (int nt = 0; nt < 8; nt++) {
            int col = n0 + wn + nt * 8 + 2 * c_;
            float bv0 = bias[col], bv1 = bias[col + 1];
            float v0 = acc[mt][nt][0] + bv0;
            float v1 = acc[mt][nt][1] + bv1;
            float v2 = acc[mt][nt][2] + bv0;
            float v3 = acc[mt][nt][3] + bv1;
            if (GELU) {
                v0 *= normcdff(v0); v1 *= normcdff(v1);
                v2 *= normcdff(v2); v3 *= normcdff(v3);
                *(float2*)&C[(size_t)r0       * HID + col] = make_float2(v0, v1);
                *(float2*)&C[(size_t)(r0 + 8) * HID + col] = make_float2(v2, v3);
            } else if (HEADM) {
                int h = col >> 6, d = col & 63;
                int b0r = r0 >> 11, s0 = r0 & 2047;
                size_t dst0 = ((size_t)(b0r * NH + h) * SEQ + s0) * 64 + d;
                size_t dst1 = dst0 + 8 * 64;
                *(float2*)&C[dst0] = make_float2(f2tf_f(v0), f2tf_f(v1));
                *(float2*)&C[dst1] = make_float2(f2tf_f(v2), f2tf_f(v3));
            } else {
                *(float2*)&C[(size_t)r0       * HID + col] = make_float2(f2tf_f(v0), f2tf_f(v1));
                *(float2*)&C[(size_t)(r0 + 8) * HID + col] = make_float2(f2tf_f(v2), f2tf_f(v3));
            }
        }
    }
}

template<bool GELU, bool HEADM>
__global__ __launch_bounds__(256, 2) void gemm7(
    const float* __restrict__ A, const float* __restrict__ W,
    const float* __restrict__ bias, float* __restrict__ C)
{
    gemm_body<GELU, HEADM>(A, W, bias, C);
}

__global__ __launch_bounds__(256, 2) void gemm7_qkv(
    const float* __restrict__ A, const float* __restrict__ Wr,
    const float* __restrict__ b0, const float* __restrict__ b1, const float* __restrict__ b2,
    float* __restrict__ C0, float* __restrict__ C1, float* __restrict__ C2)
{
    const int z = blockIdx.z;
    const float* W = Wr + (size_t)z * HID * HID;
    const float* bb = z == 0 ? b0 : (z == 1 ? b1 : b2);
    float* C = z == 0 ? C0 : (z == 1 ? C1 : C2);
    gemm_body<false, true>(A, W, bb, C);
}

// ---------------------------------------------------------------------------
// Flash attention, unnormalized streaming softmax (R7 attn5, unchanged).
// Block = (b, h, 128-q-tile), 128 thr / 4 warps, warp = 32 q-rows, 2 CTA/SM.
// Smem: Ps[128][68] + K[2][64][68] + V[2][64][72] + ms[2][64] = 107008 B.
// ---------------------------------------------------------------------------
#define A_KS (64*68)
#define A_VS (64*72)
#define A_P_OFF 0
#define A_K_OFF (128*68)
#define A_V_OFF (A_K_OFF + 2*A_KS)
#define A_M_OFF (A_V_OFF + 2*A_VS)
#define A_SMEM_BYTES ((A_M_OFF + 128)*4)

__global__ __launch_bounds__(128, 2) void attn5(
    const float* __restrict__ qh, const float* __restrict__ kh,
    const float* __restrict__ vh, const float* __restrict__ mask,
    float* __restrict__ ctx)
{
    extern __shared__ float sa[];
    float* Ps   = sa + A_P_OFF;
    float* Kbuf = sa + A_K_OFF;
    float* Vbuf = sa + A_V_OFF;
    float* msb  = sa + A_M_OFF;

    const int tid  = threadIdx.x;
    const int lane = tid & 31;
    const int warp = tid >> 5;
    const int c_   = lane & 3;
    const int q_   = lane >> 2;
    const int b    = blockIdx.z;
    const int h    = blockIdx.y;
    const int q0   = blockIdx.x * 128;
    const int bS   = b * SEQ;
    const int bh   = b * NH + h;
    const int wq   = warp * 32;
    const float scale2 = 0.125f * 1.44269504f;
    const float pen2   = 1e9f * 1.44269504f;

    const int prow = tid >> 4;
    const int pch  = (tid & 15) * 4;

    const float* kbase0 = &kh[(size_t)bh * SEQ * 64];
    const float* vbase0 = &vh[(size_t)bh * SEQ * 64];

    {
        #pragma unroll
        for (int i = 0; i < 8; i++) {
            int row = prow + i * 8;
            cpa16(smaddr(&Kbuf[row * 68 + pch]), kbase0 + (size_t)row * 64 + pch);
            cpa16(smaddr(&Vbuf[row * 72 + pch]), vbase0 + (size_t)row * 64 + pch);
        }
        if (tid < 16) cpa16(smaddr(&msb[tid * 4]), &mask[bS + tid * 4]);
        cpa_commit();
    }

    uint32_t qa[2][8][4];
    #pragma unroll
    for (int mt = 0; mt < 2; mt++) {
        const float* p0 = &qh[((size_t)bh * SEQ + q0 + wq + mt * 16 + q_) * 64];
        const float* p1 = p0 + 8 * 64;
        #pragma unroll
        for (int ksi = 0; ksi < 8; ksi++) {
            qa[mt][ksi][0] = __float_as_uint(p0[ksi * 8 + c_]);
            qa[mt][ksi][1] = __float_as_uint(p1[ksi * 8 + c_]);
            qa[mt][ksi][2] = __float_as_uint(p0[ksi * 8 + c_ + 4]);
            qa[mt][ksi][3] = __float_as_uint(p1[ksi * 8 + c_ + 4]);
        }
    }

    float mq[2][2];
    #pragma unroll
    for (int mt = 0; mt < 2; mt++) {
        mq[mt][0] = mask[bS + q0 + wq + mt * 16 + q_];
        mq[mt][1] = mask[bS + q0 + wq + mt * 16 + q_ + 8];
    }

    float l[2][2] = {};
    float o[2][8][4] = {};

    const int nT = SEQ / 64;
    for (int t = 0; t < nT; t++) {
        const int cur = t & 1;
        if (t + 1 < nT) {
            const int k0 = (t + 1) * 64;
            float* Kd = Kbuf + (cur ^ 1) * A_KS;
            float* Vd = Vbuf + (cur ^ 1) * A_VS;
            const float* kb = kbase0 + (size_t)k0 * 64;
            const float* vb = vbase0 + (size_t)k0 * 64;
            #pragma unroll
            for (int i = 0; i < 8; i++) {
                int row = prow + i * 8;
                cpa16(smaddr(&Kd[row * 68 + pch]), kb + (size_t)row * 64 + pch);
                cpa16(smaddr(&Vd[row * 72 + pch]), vb + (size_t)row * 64 + pch);
            }
            if (tid < 16) cpa16(smaddr(&msb[(cur ^ 1) * 64 + tid * 4]), &mask[bS + k0 + tid * 4]);
        }
        cpa_commit();
        cpa_wait1();
        __syncthreads();

        float* Kc = Kbuf + cur * A_KS;
        float* Vc = Vbuf + cur * A_VS;
        const float* mc = msb + cur * 64;

        // ---- S = Q K^T (warp: 32x64)
        float s[2][8][4] = {};
        #pragma unroll
        for (int ksi = 0; ksi < 8; ksi++) {
            #pragma unroll
            for (int nt = 0; nt < 8; nt++) {
                uint32_t b0 = __float_as_uint(Kc[(nt * 8 + q_) * 68 + ksi * 8 + c_]);
                uint32_t b1 = __float_as_uint(Kc[(nt * 8 + q_) * 68 + ksi * 8 + c_ + 4]);
                mma_tf32(s[0][nt], qa[0][ksi][0], qa[0][ksi][1], qa[0][ksi][2], qa[0][ksi][3], b0, b1);
                mma_tf32(s[1][nt], qa[1][ksi][0], qa[1][ksi][1], qa[1][ksi][2], qa[1][ksi][3], b0, b1);
            }
        }

        // ---- mask + exp2 (no max subtraction), accumulate row sums
        #pragma unroll
        for (int mt = 0; mt < 2; mt++) {
            #pragma unroll
            for (int nt = 0; nt < 8; nt++) {
                float mk0 = mc[nt * 8 + 2 * c_];
                float mk1 = mc[nt * 8 + 2 * c_ + 1];
                float e;
                e = mq[mt][0] * mk0; s[mt][nt][0] = fexp2(e * (s[mt][nt][0] * scale2) - (1.0f - e) * pen2);
                e = mq[mt][0] * mk1; s[mt][nt][1] = fexp2(e * (s[mt][nt][1] * scale2) - (1.0f - e) * pen2);
                e = mq[mt][1] * mk0; s[mt][nt][2] = fexp2(e * (s[mt][nt][2] * scale2) - (1.0f - e) * pen2);
                e = mq[mt][1] * mk1; s[mt][nt][3] = fexp2(e * (s[mt][nt][3] * scale2) - (1.0f - e) * pen2);
                l[mt][0] += s[mt][nt][0] + s[mt][nt][1];
                l[mt][1] += s[mt][nt][2] + s[mt][nt][3];
            }
        }

        // ---- P -> Ps (warp-private rows, stride 68 conflict-free for A reads)
        #pragma unroll
        for (int mt = 0; mt < 2; mt++) {
            int rr = wq + mt * 16 + q_;
            #pragma unroll
            for (int nt = 0; nt < 8; nt++) {
                *(uint2*)&Ps[rr * 68 + nt * 8 + 2 * c_] =
                    make_uint2(f2tf(s[mt][nt][0]), f2tf(s[mt][nt][1]));
                *(uint2*)&Ps[(rr + 8) * 68 + nt * 8 + 2 * c_] =
                    make_uint2(f2tf(s[mt][nt][2]), f2tf(s[mt][nt][3]));
            }
        }
        __syncwarp();

        // ---- O += P V (warp: 32x64)
        #pragma unroll
        for (int ksi = 0; ksi < 8; ksi++) {
            uint32_t a[2][4];
            #pragma unroll
            for (int mt = 0; mt < 2; mt++) {
                int rr = wq + mt * 16 + q_;
                a[mt][0] = __float_as_uint(Ps[rr * 68 + ksi * 8 + c_]);
                a[mt][1] = __float_as_uint(Ps[(rr + 8) * 68 + ksi * 8 + c_]);
                a[mt][2] = __float_as_uint(Ps[rr * 68 + ksi * 8 + c_ + 4]);
                a[mt][3] = __float_as_uint(Ps[(rr + 8) * 68 + ksi * 8 + c_ + 4]);
            }
            #pragma unroll
            for (int nt = 0; nt < 8; nt++) {
                uint32_t b0 = __float_as_uint(Vc[(ksi * 8 + c_) * 72 + nt * 8 + q_]);
                uint32_t b1 = __float_as_uint(Vc[(ksi * 8 + c_ + 4) * 72 + nt * 8 + q_]);
                mma_tf32(o[0][nt], a[0][0], a[0][1], a[0][2], a[0][3], b0, b1);
                mma_tf32(o[1][nt], a[1][0], a[1][1], a[1][2], a[1][3], b0, b1);
            }
        }
        __syncthreads();
    }

    #pragma unroll
    for (int mt = 0; mt < 2; mt++) {
        #pragma unroll
        for (int half = 0; half < 2; half++) {
            l[mt][half] += __shfl_xor_sync(0xffffffffu, l[mt][half], 1);
            l[mt][half] += __shfl_xor_sync(0xffffffffu, l[mt][half], 2);
        }
    }

    #pragma unroll
    for (int mt = 0; mt < 2; mt++) {
        float inv0 = 1.0f / l[mt][0], inv1 = 1.0f / l[mt][1];
        int gr = bS + q0 + wq + mt * 16 + q_;
        #pragma unroll
        for (int nt = 0; nt < 8; nt++) {
            int col = h * DH + nt * 8 + 2 * c_;
            *(float2*)&ctx[(size_t)gr * HID + col] =
                make_float2(f2tf_f(o[mt][nt][0] * inv0), f2tf_f(o[mt][nt][1] * inv0));
            *(float2*)&ctx[(size_t)(gr + 8) * HID + col] =
                make_float2(f2tf_f(o[mt][nt][2] * inv1), f2tf_f(o[mt][nt][3] * inv1));
        }
    }
}

// ---------------------------------------------------------------------------
extern "C" void kernel_launch(void* const* d_in, const int* in_sizes, int n_in,
                              void* d_out, int out_size)
{
    const float* hs   = (const float*)d_in[0];
    const float* mask = (const float*)d_in[1];
    const float* Wq   = (const float*)d_in[2];
    const float* bq   = (const float*)d_in[3];
    const float* Wk   = (const float*)d_in[4];
    const float* bk   = (const float*)d_in[5];
    const float* Wv   = (const float*)d_in[6];
    const float* bv   = (const float*)d_in[7];
    const float* Wo   = (const float*)d_in[8];
    const float* bo   = (const float*)d_in[9];
    float* out = (float*)d_out;

    float *hsr, *wr, *qh, *kh, *vh, *cb;
    cudaGetSymbolAddress((void**)&hsr, g_hsr);
    cudaGetSymbolAddress((void**)&wr,  g_wr);
    cudaGetSymbolAddress((void**)&qh,  g_qh);
    cudaGetSymbolAddress((void**)&kh,  g_kh);
    cudaGetSymbolAddress((void**)&vh,  g_vh);
    cudaGetSymbolAddress((void**)&cb,  g_ctx);

    cudaFuncSetAttribute(gemm7_qkv,          cudaFuncAttributeMaxDynamicSharedMemorySize, G_SMEM_BYTES);
    cudaFuncSetAttribute(gemm7<true,false>,  cudaFuncAttributeMaxDynamicSharedMemorySize, G_SMEM_BYTES);
    cudaFuncSetAttribute(attn5,              cudaFuncAttributeMaxDynamicSharedMemorySize, A_SMEM_BYTES);

    // --- pre-round inputs to tf32 ---
    round_hs<<<(MTOT * HID / 4 + 255) / 256, 256>>>(hs, hsr, MTOT * HID / 4);
    dim3 wgrid((HID * HID / 4 + 255) / 256, 4);
    round_w4<<<wgrid, 256>>>(Wq, Wk, Wv, Wo, wr);

    // --- fused QKV projections (write head-major rounded) ---
    dim3 qkvgrid(HID / 128, MTOT / 128, 3);   // (6, 64, 3)
    gemm7_qkv<<<qkvgrid, 256, G_SMEM_BYTES>>>(
        hsr, wr, bq, bk, bv, qh, kh, vh);

    // --- attention ---
    dim3 agrid(SEQ / 128, NH, BATCH);    // (16, 12, 4) = 768 blocks
    attn5<<<agrid, 128, A_SMEM_BYTES>>>(qh, kh, vh, mask, cb);

    // --- output projection + GELU ---
    dim3 ggrid(HID / 128, MTOT / 128);   // (6, 64)
    gemm7<true,false><<<ggrid, 256, G_SMEM_BYTES>>>(cb, wr + 3 * (size_t)HID * HID, bo, out);
}

// round 11
// speedup vs baseline: 1.4883x; 1.2980x over previous
#include <cuda_runtime.h>
#include <cuda_fp16.h>
#include <math.h>
#include <stdint.h>

#define HID   768
#define NH    12
#define DH    64
#define BATCH 4
#define SEQ   2048
#define MTOT  (BATCH*SEQ)   // 8192

// Scratch (allocation-free rule: __device__ globals)
__device__ float  g_hsr[MTOT*HID];       // hs rounded to tf32
__device__ float  g_wr[4][HID*HID];      // Wq,Wk,Wv,Wo rounded tf32
__device__ __half g_qh[MTOT*HID];        // q head-major fp16 [bh][s][d]
__device__ __half g_kh[MTOT*HID];        // k head-major fp16 [bh][s][d]
__device__ __half g_vht[MTOT*HID];       // v head-major TRANSPOSED fp16 [bh][d][s]
__device__ float  g_ctx[MTOT*HID];       // ctx standard layout, tf32-rounded

// ---------------------------------------------------------------------------
__device__ __forceinline__ uint32_t f2tf(float x) {
    uint32_t r;
    asm("cvt.rna.tf32.f32 %0, %1;" : "=r"(r) : "f"(x));
    return r;
}
__device__ __forceinline__ float f2tf_f(float x) {
    uint32_t u = f2tf(x); return __uint_as_float(u);
}
__device__ __forceinline__ float fexp2(float x) {
    float y;
    asm("ex2.approx.f32 %0, %1;" : "=f"(y) : "f"(x));
    return y;
}
__device__ __forceinline__ uint32_t packh2(float a, float b) {
    __half2 h = __floats2half2_rn(a, b);
    return *reinterpret_cast<uint32_t*>(&h);
}

__device__ __forceinline__ void mma_tf32(float c[4],
    uint32_t a0, uint32_t a1, uint32_t a2, uint32_t a3,
    uint32_t b0, uint32_t b1)
{
    asm volatile(
        "mma.sync.aligned.m16n8k8.row.col.f32.tf32.tf32.f32 "
        "{%0,%1,%2,%3}, {%4,%5,%6,%7}, {%8,%9}, {%0,%1,%2,%3};"
        : "+f"(c[0]), "+f"(c[1]), "+f"(c[2]), "+f"(c[3])
        : "r"(a0), "r"(a1), "r"(a2), "r"(a3), "r"(b0), "r"(b1));
}
__device__ __forceinline__ void mma_f16(float c[4],
    uint32_t a0, uint32_t a1, uint32_t a2, uint32_t a3,
    uint32_t b0, uint32_t b1)
{
    asm volatile(
        "mma.sync.aligned.m16n8k16.row.col.f32.f16.f16.f32 "
        "{%0,%1,%2,%3}, {%4,%5,%6,%7}, {%8,%9}, {%0,%1,%2,%3};"
        : "+f"(c[0]), "+f"(c[1]), "+f"(c[2]), "+f"(c[3])
        : "r"(a0), "r"(a1), "r"(a2), "r"(a3), "r"(b0), "r"(b1));
}

__device__ __forceinline__ uint32_t smaddr(const void* p) {
    return (uint32_t)__cvta_generic_to_shared(p);
}
__device__ __forceinline__ void cpa16(uint32_t dst, const void* src) {
    asm volatile("cp.async.cg.shared.global [%0], [%1], 16;" :: "r"(dst), "l"(src));
}
__device__ __forceinline__ void cpa_commit() {
    asm volatile("cp.async.commit_group;" ::: "memory");
}
__device__ __forceinline__ void cpa_wait1() {
    asm volatile("cp.async.wait_group 1;" ::: "memory");
}

// ---------------------------------------------------------------------------
// Pre-round kernels (tf32 inputs for the projection GEMMs)
// ---------------------------------------------------------------------------
__global__ void round_hs(const float* __restrict__ in, float* __restrict__ out, int n4)
{
    int i = blockIdx.x * blockDim.x + threadIdx.x;
    if (i < n4) {
        float4 v = ((const float4*)in)[i];
        ((float4*)out)[i] = make_float4(f2tf_f(v.x), f2tf_f(v.y), f2tf_f(v.z), f2tf_f(v.w));
    }
}
__global__ void round_w4(const float* __restrict__ w0, const float* __restrict__ w1,
                         const float* __restrict__ w2, const float* __restrict__ w3,
                         float* __restrict__ out)
{
    const int wi = blockIdx.y;
    const float* src = wi == 0 ? w0 : (wi == 1 ? w1 : (wi == 2 ? w2 : w3));
    float* dst = out + (size_t)wi * HID * HID;
    int i = blockIdx.x * blockDim.x + threadIdx.x;
    if (i < HID * HID / 4) {
        float4 v = ((const float4*)src)[i];
        ((float4*)dst)[i] = make_float4(f2tf_f(v.x), f2tf_f(v.y), f2tf_f(v.z), f2tf_f(v.w));
    }
}

// ---------------------------------------------------------------------------
// GEMM: C = A[M,768] @ W[768,768] + bias. Inputs pre-rounded tf32.
// BM=128, BN=128, BK=32. 256 thr / 8 warps (4m x 2n), warp tile 32x64.
// 2 CTA/SM (16 warps/SM). cp.async 2-stage.
// mode 0: fp32 out + exact GELU (O-proj)
// mode 1: fp16 head-major out [bh][s][d]   (Q, K)
// mode 2: fp16 transposed out [bh][d][s]   (V)
// ---------------------------------------------------------------------------
#define G_AS (128*36)
#define G_BS (32*136)
#define G_SMEM_BYTES ((2*G_AS + 2*G_BS)*4)

__device__ __forceinline__ void gemm_body(
    const float* __restrict__ A, const float* __restrict__ W,
    const float* __restrict__ bias, float* __restrict__ Cf,
    __half* __restrict__ Ch, int mode)
{
    extern __shared__ float sg[];
    float* Asm = sg;                 // [2][128][36]
    float* Bsm = sg + 2 * G_AS;      // [2][32][136]

    const int tid  = threadIdx.x;
    const int lane = tid & 31;
    const int warp = tid >> 5;
    const int wm   = (warp >> 1) * 32;
    const int wn   = (warp & 1) * 64;
    const int m0   = blockIdx.y * 128;
    const int n0   = blockIdx.x * 128;
    const int c_   = lane & 3;
    const int q_   = lane >> 2;

    const int ar = tid >> 3, ac = (tid & 7) * 4;
    const int br = tid >> 5, bc = (tid & 31) * 4;

    float acc[2][8][4] = {};
    const int nT = HID / 32;   // 24

    {
        #pragma unroll
        for (int i = 0; i < 4; i++) {
            int row = ar + i * 32;
            cpa16(smaddr(&Asm[row * 36 + ac]), &A[(size_t)(m0 + row) * HID + ac]);
        }
        #pragma unroll
        for (int i = 0; i < 4; i++) {
            int row = br + i * 8;
            cpa16(smaddr(&Bsm[row * 136 + bc]), &W[(size_t)row * HID + n0 + bc]);
        }
        cpa_commit();
    }

    for (int t = 0; t < nT; t++) {
        const int cur = t & 1;
        if (t + 1 < nT) {
            const int k0 = (t + 1) * 32;
            float* Ad = Asm + (cur ^ 1) * G_AS;
            float* Bd = Bsm + (cur ^ 1) * G_BS;
            #pragma unroll
            for (int i = 0; i < 4; i++) {
                int row = ar + i * 32;
                cpa16(smaddr(&Ad[row * 36 + ac]), &A[(size_t)(m0 + row) * HID + k0 + ac]);
            }
            #pragma unroll
            for (int i = 0; i < 4; i++) {
                int row = br + i * 8;
                cpa16(smaddr(&Bd[row * 136 + bc]), &W[(size_t)(k0 + row) * HID + n0 + bc]);
            }
        }
        cpa_commit();
        cpa_wait1();
        __syncthreads();

        const float* Ac = Asm + cur * G_AS;
        const float* Bc = Bsm + cur * G_BS;
        #pragma unroll
        for (int ksi = 0; ksi < 4; ksi++) {
            uint32_t a[2][4];
            #pragma unroll
            for (int mt = 0; mt < 2; mt++) {
                int r = wm + mt * 16 + q_;
                a[mt][0] = __float_as_uint(Ac[r * 36 + ksi * 8 + c_]);
                a[mt][1] = __float_as_uint(Ac[(r + 8) * 36 + ksi * 8 + c_]);
                a[mt][2] = __float_as_uint(Ac[r * 36 + ksi * 8 + c_ + 4]);
                a[mt][3] = __float_as_uint(Ac[(r + 8) * 36 + ksi * 8 + c_ + 4]);
            }
            #pragma unroll
            for (int nt = 0; nt < 8; nt++) {
                uint32_t b0 = __float_as_uint(Bc[(ksi * 8 + c_) * 136 + wn + nt * 8 + q_]);
                uint32_t b1 = __float_as_uint(Bc[(ksi * 8 + c_ + 4) * 136 + wn + nt * 8 + q_]);
                mma_tf32(acc[0][nt], a[0][0], a[0][1], a[0][2], a[0][3], b0, b1);
                mma_tf32(acc[1][nt], a[1][0], a[1][1], a[1][2], a[1][3], b0, b1);
            }
        }
        __syncthreads();
    }

    // epilogue
    #pragma unroll
    for (int mt = 0; mt < 2; mt++) {
        int r0 = m0 + wm + mt * 16 + q_;
        int bb = r0 >> 11, s0 = r0 & 2047;
        #pragma unroll
        for (int nt = 0; nt < 8; nt++) {
            int col = n0 + wn + nt * 8 + 2 * c_;
            float bv0 = bias[col], bv1 = bias[col + 1];
            float v0 = acc[mt][nt][0] + bv0;
            float v1 = acc[mt][nt][1] + bv1;
            float v2 = acc[mt][nt][2] + bv0;
            float v3 = acc[mt][nt][3] + bv1;
            if (mode == 0) {
                v0 *= normcdff(v0); v1 *= normcdff(v1);
                v2 *= normcdff(v2); v3 *= normcdff(v3);
                *(float2*)&Cf[(size_t)r0       * HID + col] = make_float2(v0, v1);
                *(float2*)&Cf[(size_t)(r0 + 8) * HID + col] = make_float2(v2, v3);
            } else {
                int hh = col >> 6, d = col & 63;
                if (mode == 1) {
                    __half* base = Ch + ((size_t)(bb * NH + hh) * SEQ) * 64;
                    *(__half2*)(base + (size_t)s0 * 64 + d)       = __floats2half2_rn(v0, v1);
                    *(__half2*)(base + (size_t)(s0 + 8) * 64 + d) = __floats2half2_rn(v2, v3);
                } else {
                    __half* base = Ch + ((size_t)(bb * NH + hh) * 64) * SEQ;
                    base[(size_t)d       * SEQ + s0]     = __float2half_rn(v0);
                    base[(size_t)(d + 1) * SEQ + s0]     = __float2half_rn(v1);
                    base[(size_t)d       * SEQ + s0 + 8] = __float2half_rn(v2);
                    base[(size_t)(d + 1) * SEQ + s0 + 8] = __float2half_rn(v3);
                }
            }
        }
    }
}

__global__ __launch_bounds__(256, 2) void gemm8_qkv(
    const float* __restrict__ A, const float* __restrict__ Wr,
    const float* __restrict__ b0, const float* __restrict__ b1, const float* __restrict__ b2,
    __half* __restrict__ qh, __half* __restrict__ kh, __half* __restrict__ vht)
{
    const int z = blockIdx.z;
    const float* W = Wr + (size_t)z * HID * HID;
    const float* bb = z == 0 ? b0 : (z == 1 ? b1 : b2);
    __half* Ch = z == 0 ? qh : (z == 1 ? kh : vht);
    gemm_body(A, W, bb, nullptr, Ch, z == 2 ? 2 : 1);
}

__global__ __launch_bounds__(256, 2) void gemm8_o(
    const float* __restrict__ A, const float* __restrict__ W,
    const float* __restrict__ bias, float* __restrict__ C)
{
    gemm_body(A, W, bias, C, nullptr, 0);
}

// ---------------------------------------------------------------------------
// Flash attention, fp16 mma (m16n8k16), unnormalized streaming softmax.
// Block = (b, h, 128-q-tile), 128 thr / 4 warps, warp = 32 q-rows, 2 CTA/SM.
// Q fragments in registers (fp16). P passes register-direct from QK C-frags
// to PV A-frags (no smem round-trip). K smem [key][d], V smem transposed
// [d][key]. 128-key double-buffered tiles (2 x 64-key compute subtiles).
// Smem: K[2][128][72h] + V[2][64][136h] + ms[2][128]f = 72704 B.
// ---------------------------------------------------------------------------
#define TSK 128
#define K_ROWB 144
#define V_ROWB 272
#define KBUF_B (128*K_ROWB)               // 18432
#define VBUF_B (64*V_ROWB)                // 17408
#define AV_OFF (2*KBUF_B)                 // 36864
#define AM_OFF (AV_OFF + 2*VBUF_B)        // 71680
#define A_SMEM_BYTES (AM_OFF + 2*TSK*4)   // 72704

__global__ __launch_bounds__(128, 2) void attn7(
    const __half* __restrict__ qh, const __half* __restrict__ kh,
    const __half* __restrict__ vht, const float* __restrict__ mask,
    float* __restrict__ ctx)
{
    extern __shared__ char smc[];
    float* msb = (float*)(smc + AM_OFF);

    const int tid  = threadIdx.x;
    const int lane = tid & 31;
    const int warp = tid >> 5;
    const int c_   = lane & 3;
    const int q_   = lane >> 2;
    const int b    = blockIdx.z;
    const int h    = blockIdx.y;
    const int q0   = blockIdx.x * 128;
    const int bS   = b * SEQ;
    const int bh   = b * NH + h;
    const int wq   = warp * 32;
    const float scale2 = 0.125f * 1.44269504f;   // fold log2e into scale
    const float pen2   = 1e9f * 1.44269504f;

    const __half* kbase = kh  + (size_t)bh * SEQ * 64;   // [key][d]
    const __half* vbase = vht + (size_t)bh * 64 * SEQ;   // [d][key]

    // producer fill for key-tile starting at k0 into buffer buf
    #define AFILL(buf, k0_) do {                                               \
        const int _k0 = (k0_);                                                 \
        char* Kd = smc + (buf) * KBUF_B;                                       \
        char* Vd = smc + AV_OFF + (buf) * VBUF_B;                              \
        _Pragma("unroll")                                                      \
        for (int i = 0; i < 8; i++) {                                          \
            int idx = tid + i * 128;                                           \
            int kr = idx >> 3, ch = idx & 7;                                   \
            cpa16(smaddr(Kd + kr * K_ROWB + ch * 16),                          \
                  kbase + ((size_t)(_k0 + kr)) * 64 + ch * 8);                 \
            int vr = idx >> 4, vch = idx & 15;                                 \
            cpa16(smaddr(Vd + vr * V_ROWB + vch * 16),                         \
                  vbase + (size_t)vr * SEQ + _k0 + vch * 8);                   \
        }                                                                      \
        if (tid < 32) cpa16(smaddr((char*)(msb + (buf) * TSK) + tid * 16),     \
                            mask + bS + _k0 + tid * 4);                        \
    } while (0)

    AFILL(0, 0);
    cpa_commit();

    // Q fragments in registers (fp16): 2 m-tiles x 4 k16-chunks x 4 regs
    uint32_t qa[2][4][4];
    #pragma unroll
    for (int mt = 0; mt < 2; mt++) {
        const __half* p0 = qh + ((size_t)bh * SEQ + q0 + wq + mt * 16 + q_) * 64;
        const __half* p1 = p0 + 8 * 64;
        #pragma unroll
        for (int ksi = 0; ksi < 4; ksi++) {
            qa[mt][ksi][0] = *(const uint32_t*)(p0 + 16 * ksi + 2 * c_);
            qa[mt][ksi][1] = *(const uint32_t*)(p1 + 16 * ksi + 2 * c_);
            qa[mt][ksi][2] = *(const uint32_t*)(p0 + 16 * ksi + 2 * c_ + 8);
            qa[mt][ksi][3] = *(const uint32_t*)(p1 + 16 * ksi + 2 * c_ + 8);
        }
    }

    float mq[2][2];
    #pragma unroll
    for (int mt = 0; mt < 2; mt++) {
        mq[mt][0] = mask[bS + q0 + wq + mt * 16 + q_];
        mq[mt][1] = mask[bS + q0 + wq + mt * 16 + q_ + 8];
    }

    float l[2][2] = {};
    float o[2][8][4] = {};

    const int nT = SEQ / TSK;   // 16
    for (int t = 0; t < nT; t++) {
        const int cur = t & 1;
        if (t + 1 < nT) { AFILL(cur ^ 1, (t + 1) * TSK); }
        cpa_commit();
        cpa_wait1();
        __syncthreads();

        const uint32_t* Kw = (const uint32_t*)(smc + cur * KBUF_B);
        const uint32_t* Vw = (const uint32_t*)(smc + AV_OFF + cur * VBUF_B);
        const float* mc = msb + cur * TSK;

        #pragma unroll
        for (int sub = 0; sub < 2; sub++) {
            // ---- S = Q K^T  (warp 32 x 64 keys), fp16 k16 mma
            float s[2][8][4] = {};
            #pragma unroll
            for (int ksi = 0; ksi < 4; ksi++) {
                #pragma unroll
                for (int nt = 0; nt < 8; nt++) {
                    int kw = (sub * 64 + nt * 8 + q_) * 36 + ksi * 8 + c_;
                    uint32_t b0 = Kw[kw];
                    uint32_t b1 = Kw[kw + 4];
                    mma_f16(s[0][nt], qa[0][ksi][0], qa[0][ksi][1], qa[0][ksi][2], qa[0][ksi][3], b0, b1);
                    mma_f16(s[1][nt], qa[1][ksi][0], qa[1][ksi][1], qa[1][ksi][2], qa[1][ksi][3], b0, b1);
                }
            }

            // ---- mask + exp2 (no max subtraction), accumulate row sums
            #pragma unroll
            for (int mt = 0; mt < 2; mt++) {
                #pragma unroll
                for (int nt = 0; nt < 8; nt++) {
                    float mk0 = mc[sub * 64 + nt * 8 + 2 * c_];
                    float mk1 = mc[sub * 64 + nt * 8 + 2 * c_ + 1];
                    float e;
                    e = mq[mt][0] * mk0; s[mt][nt][0] = fexp2(e * (s[mt][nt][0] * scale2) - (1.0f - e) * pen2);
                    e = mq[mt][0] * mk1; s[mt][nt][1] = fexp2(e * (s[mt][nt][1] * scale2) - (1.0f - e) * pen2);
                    e = mq[mt][1] * mk0; s[mt][nt][2] = fexp2(e * (s[mt][nt][2] * scale2) - (1.0f - e) * pen2);
                    e = mq[mt][1] * mk1; s[mt][nt][3] = fexp2(e * (s[mt][nt][3] * scale2) - (1.0f - e) * pen2);
                    l[mt][0] += s[mt][nt][0] + s[mt][nt][1];
                    l[mt][1] += s[mt][nt][2] + s[mt][nt][3];
                }
            }

            // ---- O += P V: P packs register-direct into A-fragments
            #pragma unroll
            for (int ksi = 0; ksi < 4; ksi++) {
                uint32_t a[2][4];
                #pragma unroll
                for (int mt = 0; mt < 2; mt++) {
                    a[mt][0] = packh2(s[mt][2 * ksi][0],     s[mt][2 * ksi][1]);
                    a[mt][1] = packh2(s[mt][2 * ksi][2],     s[mt][2 * ksi][3]);
                    a[mt][2] = packh2(s[mt][2 * ksi + 1][0], s[mt][2 * ksi + 1][1]);
                    a[mt][3] = packh2(s[mt][2 * ksi + 1][2], s[mt][2 * ksi + 1][3]);
                }
                #pragma unroll
                for (int nt = 0; nt < 8; nt++) {
                    int vw = (q_ + nt * 8) * 68 + sub * 32 + ksi * 8 + c_;
                    uint32_t b0 = Vw[vw];
                    uint32_t b1 = Vw[vw + 4];
                    mma_f16(o[0][nt], a[0][0], a[0][1], a[0][2], a[0][3], b0, b1);
                    mma_f16(o[1][nt], a[1][0], a[1][1], a[1][2], a[1][3], b0, b1);
                }
            }
        }
        __syncthreads();   // all warps done with cur buffers before next AFILL
    }

    // ---- final row-sum reduction over 4-lane group, normalize, write
    #pragma unroll
    for (int mt = 0; mt < 2; mt++) {
        #pragma unroll
        for (int half = 0; half < 2; half++) {
            l[mt][half] += __shfl_xor_sync(0xffffffffu, l[mt][half], 1);
            l[mt][half] += __shfl_xor_sync(0xffffffffu, l[mt][half], 2);
        }
    }

    #pragma unroll
    for (int mt = 0; mt < 2; mt++) {
        float inv0 = 1.0f / l[mt][0], inv1 = 1.0f / l[mt][1];
        int gr = bS + q0 + wq + mt * 16 + q_;
        #pragma unroll
        for (int nt = 0; nt < 8; nt++) {
            int col = h * DH + nt * 8 + 2 * c_;
            *(float2*)&ctx[(size_t)gr * HID + col] =
                make_float2(f2tf_f(o[mt][nt][0] * inv0), f2tf_f(o[mt][nt][1] * inv0));
            *(float2*)&ctx[(size_t)(gr + 8) * HID + col] =
                make_float2(f2tf_f(o[mt][nt][2] * inv1), f2tf_f(o[mt][nt][3] * inv1));
        }
    }
    #undef AFILL
}

// ---------------------------------------------------------------------------
extern "C" void kernel_launch(void* const* d_in, const int* in_sizes, int n_in,
                              void* d_out, int out_size)
{
    const float* hs   = (const float*)d_in[0];
    const float* mask = (const float*)d_in[1];
    const float* Wq   = (const float*)d_in[2];
    const float* bq   = (const float*)d_in[3];
    const float* Wk   = (const float*)d_in[4];
    const float* bk   = (const float*)d_in[5];
    const float* Wv   = (const float*)d_in[6];
    const float* bv   = (const float*)d_in[7];
    const float* Wo   = (const float*)d_in[8];
    const float* bo   = (const float*)d_in[9];
    float* out = (float*)d_out;

    float *hsr, *wr, *cb;
    __half *qh, *kh, *vht;
    cudaGetSymbolAddress((void**)&hsr, g_hsr);
    cudaGetSymbolAddress((void**)&wr,  g_wr);
    cudaGetSymbolAddress((void**)&qh,  g_qh);
    cudaGetSymbolAddress((void**)&kh,  g_kh);
    cudaGetSymbolAddress((void**)&vht, g_vht);
    cudaGetSymbolAddress((void**)&cb,  g_ctx);

    cudaFuncSetAttribute(gemm8_qkv, cudaFuncAttributeMaxDynamicSharedMemorySize, G_SMEM_BYTES);
    cudaFuncSetAttribute(gemm8_o,   cudaFuncAttributeMaxDynamicSharedMemorySize, G_SMEM_BYTES);
    cudaFuncSetAttribute(attn7,     cudaFuncAttributeMaxDynamicSharedMemorySize, A_SMEM_BYTES);

    // --- pre-round inputs to tf32 ---
    round_hs<<<(MTOT * HID / 4 + 255) / 256, 256>>>(hs, hsr, MTOT * HID / 4);
    dim3 wgrid((HID * HID / 4 + 255) / 256, 4);
    round_w4<<<wgrid, 256>>>(Wq, Wk, Wv, Wo, wr);

    // --- fused QKV projections (fp16 head-major Q/K, fp16 transposed V) ---
    dim3 qkvgrid(HID / 128, MTOT / 128, 3);   // (6, 64, 3)
    gemm8_qkv<<<qkvgrid, 256, G_SMEM_BYTES>>>(hsr, wr, bq, bk, bv, qh, kh, vht);

    // --- attention (fp16 mma) ---
    dim3 agrid(SEQ / 128, NH, BATCH);    // (16, 12, 4) = 768 blocks
    attn7<<<agrid, 128, A_SMEM_BYTES>>>(qh, kh, vht, mask, cb);

    // --- output projection + GELU (tf32) ---
    dim3 ggrid(HID / 128, MTOT / 128);   // (6, 64)
    gemm8_o<<<ggrid, 256, G_SMEM_BYTES>>>(cb, wr + 3 * (size_t)HID * HID, bo, out);
}

// round 12
// speedup vs baseline: 1.9254x; 1.2937x over previous
#include <cuda_runtime.h>
#include <cuda_fp16.h>
#include <math.h>
#include <stdint.h>

#define HID   768
#define NH    12
#define DH    64
#define BATCH 4
#define SEQ   2048
#define MTOT  (BATCH*SEQ)   // 8192

// Scratch (allocation-free rule: __device__ globals)
__device__ __half g_hsr[MTOT*HID];       // hs rounded to fp16
__device__ __half g_wt[4][HID*HID];      // W^T fp16: wt[n*HID+k] = (half)W[k*HID+n]
__device__ __half g_qh[MTOT*HID];        // q head-major fp16 [bh][s][d]
__device__ __half g_kh[MTOT*HID];        // k head-major fp16 [bh][s][d]
__device__ __half g_vht[MTOT*HID];       // v head-major TRANSPOSED fp16 [bh][d][s]
__device__ __half g_ctx[MTOT*HID];       // ctx standard layout fp16

// ---------------------------------------------------------------------------
__device__ __forceinline__ float fexp2(float x) {
    float y;
    asm("ex2.approx.f32 %0, %1;" : "=f"(y) : "f"(x));
    return y;
}
__device__ __forceinline__ uint32_t packh2(float a, float b) {
    __half2 h = __floats2half2_rn(a, b);
    return *reinterpret_cast<uint32_t*>(&h);
}

__device__ __forceinline__ void mma_f16(float c[4],
    uint32_t a0, uint32_t a1, uint32_t a2, uint32_t a3,
    uint32_t b0, uint32_t b1)
{
    asm volatile(
        "mma.sync.aligned.m16n8k16.row.col.f32.f16.f16.f32 "
        "{%0,%1,%2,%3}, {%4,%5,%6,%7}, {%8,%9}, {%0,%1,%2,%3};"
        : "+f"(c[0]), "+f"(c[1]), "+f"(c[2]), "+f"(c[3])
        : "r"(a0), "r"(a1), "r"(a2), "r"(a3), "r"(b0), "r"(b1));
}

__device__ __forceinline__ uint32_t smaddr(const void* p) {
    return (uint32_t)__cvta_generic_to_shared(p);
}
__device__ __forceinline__ void cpa16(uint32_t dst, const void* src) {
    asm volatile("cp.async.cg.shared.global [%0], [%1], 16;" :: "r"(dst), "l"(src));
}
__device__ __forceinline__ void cpa_commit() {
    asm volatile("cp.async.commit_group;" ::: "memory");
}
__device__ __forceinline__ void cpa_wait1() {
    asm volatile("cp.async.wait_group 1;" ::: "memory");
}

// ---------------------------------------------------------------------------
// Pre-processing: hs -> fp16; W -> transposed fp16 [n][k]
// ---------------------------------------------------------------------------
__global__ void round_hs_h(const float* __restrict__ in, __half* __restrict__ out, int n4)
{
    int i = blockIdx.x * blockDim.x + threadIdx.x;
    if (i < n4) {
        float4 v = ((const float4*)in)[i];
        ((uint2*)out)[i] = make_uint2(packh2(v.x, v.y), packh2(v.z, v.w));
    }
}
__global__ void transpose_w_h(const float* __restrict__ w0, const float* __restrict__ w1,
                              const float* __restrict__ w2, const float* __restrict__ w3,
                              __half* __restrict__ out)
{
    __shared__ float tile[32][33];
    const int wi = blockIdx.z;
    const float* src = wi == 0 ? w0 : (wi == 1 ? w1 : (wi == 2 ? w2 : w3));
    __half* dst = out + (size_t)wi * HID * HID;
    const int kb = blockIdx.y * 32, nb = blockIdx.x * 32;
    #pragma unroll
    for (int i = threadIdx.y; i < 32; i += 8)
        tile[i][threadIdx.x] = src[(size_t)(kb + i) * HID + nb + threadIdx.x];
    __syncthreads();
    #pragma unroll
    for (int i = threadIdx.y; i < 32; i += 8)
        dst[(size_t)(nb + i) * HID + kb + threadIdx.x] = __float2half_rn(tile[threadIdx.x][i]);
}

// ---------------------------------------------------------------------------
// fp16 GEMM: C = A[M,768] @ W + bias, A fp16 row-major, Wt fp16 [n][k].
// BM=128, BN=128, BK=64. 256 thr / 8 warps (4m x 2n), warp tile 32x64.
// mma m16n8k16. cp.async 2-stage. Smem: As[2][128][72h]+Bs[2][128][72h]=73728B.
// mode 0: fp32 out + exact GELU (final output)
// mode 1: fp16 head-major out [bh][s][d]   (Q, K)
// mode 2: fp16 transposed out [bh][d][s]   (V)
// mode 3: fp16 standard layout (unused)
// ---------------------------------------------------------------------------
#define H_TS (128*72)                 // halves per tile buffer
#define G_SMEM_BYTES (4*H_TS*2)       // 73728

__device__ __forceinline__ void gemm_body(
    const __half* __restrict__ A, const __half* __restrict__ Wt,
    const float* __restrict__ bias, float* __restrict__ Cf,
    __half* __restrict__ Ch, int mode)
{
    extern __shared__ __half sh[];
    __half* Asm = sh;                // [2][128][72]
    __half* Bsm = sh + 2 * H_TS;     // [2][128][72]

    const int tid  = threadIdx.x;
    const int lane = tid & 31;
    const int warp = tid >> 5;
    const int wm   = (warp >> 1) * 32;
    const int wn   = (warp & 1) * 64;
    const int m0   = blockIdx.y * 128;
    const int n0   = blockIdx.x * 128;
    const int c_   = lane & 3;
    const int q_   = lane >> 2;

    float acc[2][8][4] = {};
    const int nT = HID / 64;   // 12

    // producer: each thread does 4 chunks of A + 4 of B per tile
    #define GFILL(buf, k0_) do {                                              \
        const int _k0 = (k0_);                                                \
        __half* Ad = Asm + (buf) * H_TS;                                      \
        __half* Bd = Bsm + (buf) * H_TS;                                      \
        _Pragma("unroll")                                                     \
        for (int i = 0; i < 4; i++) {                                         \
            int idx = tid + i * 256;                                          \
            int row = idx >> 3, ch = idx & 7;                                 \
            cpa16(smaddr(Ad + row * 72 + ch * 8),                             \
                  A + (size_t)(m0 + row) * HID + _k0 + ch * 8);               \
            cpa16(smaddr(Bd + row * 72 + ch * 8),                             \
                  Wt + (size_t)(n0 + row) * HID + _k0 + ch * 8);              \
        }                                                                     \
    } while (0)

    GFILL(0, 0);
    cpa_commit();

    for (int t = 0; t < nT; t++) {
        const int cur = t & 1;
        if (t + 1 < nT) { GFILL(cur ^ 1, (t + 1) * 64); }
        cpa_commit();
        cpa_wait1();
        __syncthreads();

        const uint32_t* Aw = (const uint32_t*)(Asm + cur * H_TS);
        const uint32_t* Bw = (const uint32_t*)(Bsm + cur * H_TS);
        #pragma unroll
        for (int ksi = 0; ksi < 4; ksi++) {
            uint32_t a[2][4];
            #pragma unroll
            for (int mt = 0; mt < 2; mt++) {
                int r = wm + mt * 16 + q_;
                a[mt][0] = Aw[r * 36 + 8 * ksi + c_];
                a[mt][1] = Aw[(r + 8) * 36 + 8 * ksi + c_];
                a[mt][2] = Aw[r * 36 + 8 * ksi + c_ + 4];
                a[mt][3] = Aw[(r + 8) * 36 + 8 * ksi + c_ + 4];
            }
            #pragma unroll
            for (int nt = 0; nt < 8; nt++) {
                int n = wn + nt * 8 + q_;
                uint32_t b0 = Bw[n * 36 + 8 * ksi + c_];
                uint32_t b1 = Bw[n * 36 + 8 * ksi + c_ + 4];
                mma_f16(acc[0][nt], a[0][0], a[0][1], a[0][2], a[0][3], b0, b1);
                mma_f16(acc[1][nt], a[1][0], a[1][1], a[1][2], a[1][3], b0, b1);
            }
        }
        __syncthreads();
    }

    // epilogue
    #pragma unroll
    for (int mt = 0; mt < 2; mt++) {
        int r0 = m0 + wm + mt * 16 + q_;
        int bb = r0 >> 11, s0 = r0 & 2047;
        #pragma unroll
        for (int nt = 0; nt < 8; nt++) {
            int col = n0 + wn + nt * 8 + 2 * c_;
            float bv0 = bias[col], bv1 = bias[col + 1];
            float v0 = acc[mt][nt][0] + bv0;
            float v1 = acc[mt][nt][1] + bv1;
            float v2 = acc[mt][nt][2] + bv0;
            float v3 = acc[mt][nt][3] + bv1;
            if (mode == 0) {
                v0 *= normcdff(v0); v1 *= normcdff(v1);
                v2 *= normcdff(v2); v3 *= normcdff(v3);
                *(float2*)&Cf[(size_t)r0       * HID + col] = make_float2(v0, v1);
                *(float2*)&Cf[(size_t)(r0 + 8) * HID + col] = make_float2(v2, v3);
            } else {
                int hh = col >> 6, d = col & 63;
                if (mode == 1) {
                    __half* base = Ch + ((size_t)(bb * NH + hh) * SEQ) * 64;
                    *(__half2*)(base + (size_t)s0 * 64 + d)       = __floats2half2_rn(v0, v1);
                    *(__half2*)(base + (size_t)(s0 + 8) * 64 + d) = __floats2half2_rn(v2, v3);
                } else {
                    __half* base = Ch + ((size_t)(bb * NH + hh) * 64) * SEQ;
                    base[(size_t)d       * SEQ + s0]     = __float2half_rn(v0);
                    base[(size_t)(d + 1) * SEQ + s0]     = __float2half_rn(v1);
                    base[(size_t)d       * SEQ + s0 + 8] = __float2half_rn(v2);
                    base[(size_t)(d + 1) * SEQ + s0 + 8] = __float2half_rn(v3);
                }
            }
        }
    }
    #undef GFILL
}

__global__ __launch_bounds__(256, 2) void gemm9_qkv(
    const __half* __restrict__ A, const __half* __restrict__ Wt,
    const float* __restrict__ b0, const float* __restrict__ b1, const float* __restrict__ b2,
    __half* __restrict__ qh, __half* __restrict__ kh, __half* __restrict__ vht)
{
    const int z = blockIdx.z;
    const __half* W = Wt + (size_t)z * HID * HID;
    const float* bb = z == 0 ? b0 : (z == 1 ? b1 : b2);
    __half* Ch = z == 0 ? qh : (z == 1 ? kh : vht);
    gemm_body(A, W, bb, nullptr, Ch, z == 2 ? 2 : 1);
}

__global__ __launch_bounds__(256, 2) void gemm9_o(
    const __half* __restrict__ A, const __half* __restrict__ Wt,
    const float* __restrict__ bias, float* __restrict__ C)
{
    gemm_body(A, Wt, bias, C, nullptr, 0);
}

// ---------------------------------------------------------------------------
// Flash attention, fp16 mma (m16n8k16), unnormalized streaming softmax.
// (R11 attn7, unchanged except ctx output is fp16.)
// Block = (b, h, 128-q-tile), 128 thr / 4 warps, warp = 32 q-rows, 2 CTA/SM.
// Smem: K[2][128][72h] + V[2][64][136h] + ms[2][128]f = 72704 B.
// ---------------------------------------------------------------------------
#define TSK 128
#define K_ROWB 144
#define V_ROWB 272
#define KBUF_B (128*K_ROWB)
#define VBUF_B (64*V_ROWB)
#define AV_OFF (2*KBUF_B)
#define AM_OFF (AV_OFF + 2*VBUF_B)
#define A_SMEM_BYTES (AM_OFF + 2*TSK*4)

__global__ __launch_bounds__(128, 2) void attn7(
    const __half* __restrict__ qh, const __half* __restrict__ kh,
    const __half* __restrict__ vht, const float* __restrict__ mask,
    __half* __restrict__ ctx)
{
    extern __shared__ char smc[];
    float* msb = (float*)(smc + AM_OFF);

    const int tid  = threadIdx.x;
    const int lane = tid & 31;
    const int warp = tid >> 5;
    const int c_   = lane & 3;
    const int q_   = lane >> 2;
    const int b    = blockIdx.z;
    const int h    = blockIdx.y;
    const int q0   = blockIdx.x * 128;
    const int bS   = b * SEQ;
    const int bh   = b * NH + h;
    const int wq   = warp * 32;
    const float scale2 = 0.125f * 1.44269504f;
    const float pen2   = 1e9f * 1.44269504f;

    const __half* kbase = kh  + (size_t)bh * SEQ * 64;
    const __half* vbase = vht + (size_t)bh * 64 * SEQ;

    #define AFILL(buf, k0_) do {                                               \
        const int _k0 = (k0_);                                                 \
        char* Kd = smc + (buf) * KBUF_B;                                       \
        char* Vd = smc + AV_OFF + (buf) * VBUF_B;                              \
        _Pragma("unroll")                                                      \
        for (int i = 0; i < 8; i++) {                                          \
            int idx = tid + i * 128;                                           \
            int kr = idx >> 3, ch = idx & 7;                                   \
            cpa16(smaddr(Kd + kr * K_ROWB + ch * 16),                          \
                  kbase + ((size_t)(_k0 + kr)) * 64 + ch * 8);                 \
            int vr = idx >> 4, vch = idx & 15;                                 \
            cpa16(smaddr(Vd + vr * V_ROWB + vch * 16),                         \
                  vbase + (size_t)vr * SEQ + _k0 + vch * 8);                   \
        }                                                                      \
        if (tid < 32) cpa16(smaddr((char*)(msb + (buf) * TSK) + tid * 16),     \
                            mask + bS + _k0 + tid * 4);                        \
    } while (0)

    AFILL(0, 0);
    cpa_commit();

    uint32_t qa[2][4][4];
    #pragma unroll
    for (int mt = 0; mt < 2; mt++) {
        const __half* p0 = qh + ((size_t)bh * SEQ + q0 + wq + mt * 16 + q_) * 64;
        const __half* p1 = p0 + 8 * 64;
        #pragma unroll
        for (int ksi = 0; ksi < 4; ksi++) {
            qa[mt][ksi][0] = *(const uint32_t*)(p0 + 16 * ksi + 2 * c_);
            qa[mt][ksi][1] = *(const uint32_t*)(p1 + 16 * ksi + 2 * c_);
            qa[mt][ksi][2] = *(const uint32_t*)(p0 + 16 * ksi + 2 * c_ + 8);
            qa[mt][ksi][3] = *(const uint32_t*)(p1 + 16 * ksi + 2 * c_ + 8);
        }
    }

    float mq[2][2];
    #pragma unroll
    for (int mt = 0; mt < 2; mt++) {
        mq[mt][0] = mask[bS + q0 + wq + mt * 16 + q_];
        mq[mt][1] = mask[bS + q0 + wq + mt * 16 + q_ + 8];
    }

    float l[2][2] = {};
    float o[2][8][4] = {};

    const int nT = SEQ / TSK;   // 16
    for (int t = 0; t < nT; t++) {
        const int cur = t & 1;
        if (t + 1 < nT) { AFILL(cur ^ 1, (t + 1) * TSK); }
        cpa_commit();
        cpa_wait1();
        __syncthreads();

        const uint32_t* Kw = (const uint32_t*)(smc + cur * KBUF_B);
        const uint32_t* Vw = (const uint32_t*)(smc + AV_OFF + cur * VBUF_B);
        const float* mc = msb + cur * TSK;

        #pragma unroll
        for (int sub = 0; sub < 2; sub++) {
            float s[2][8][4] = {};
            #pragma unroll
            for (int ksi = 0; ksi < 4; ksi++) {
                #pragma unroll
                for (int nt = 0; nt < 8; nt++) {
                    int kw = (sub * 64 + nt * 8 + q_) * 36 + ksi * 8 + c_;
                    uint32_t b0 = Kw[kw];
                    uint32_t b1 = Kw[kw + 4];
                    mma_f16(s[0][nt], qa[0][ksi][0], qa[0][ksi][1], qa[0][ksi][2], qa[0][ksi][3], b0, b1);
                    mma_f16(s[1][nt], qa[1][ksi][0], qa[1][ksi][1], qa[1][ksi][2], qa[1][ksi][3], b0, b1);
                }
            }

            #pragma unroll
            for (int mt = 0; mt < 2; mt++) {
                #pragma unroll
                for (int nt = 0; nt < 8; nt++) {
                    float mk0 = mc[sub * 64 + nt * 8 + 2 * c_];
                    float mk1 = mc[sub * 64 + nt * 8 + 2 * c_ + 1];
                    float e;
                    e = mq[mt][0] * mk0; s[mt][nt][0] = fexp2(e * (s[mt][nt][0] * scale2) - (1.0f - e) * pen2);
                    e = mq[mt][0] * mk1; s[mt][nt][1] = fexp2(e * (s[mt][nt][1] * scale2) - (1.0f - e) * pen2);
                    e = mq[mt][1] * mk0; s[mt][nt][2] = fexp2(e * (s[mt][nt][2] * scale2) - (1.0f - e) * pen2);
                    e = mq[mt][1] * mk1; s[mt][nt][3] = fexp2(e * (s[mt][nt][3] * scale2) - (1.0f - e) * pen2);
                    l[mt][0] += s[mt][nt][0] + s[mt][nt][1];
                    l[mt][1] += s[mt][nt][2] + s[mt][nt][3];
                }
            }

            #pragma unroll
            for (int ksi = 0; ksi < 4; ksi++) {
                uint32_t a[2][4];
                #pragma unroll
                for (int mt = 0; mt < 2; mt++) {
                    a[mt][0] = packh2(s[mt][2 * ksi][0],     s[mt][2 * ksi][1]);
                    a[mt][1] = packh2(s[mt][2 * ksi][2],     s[mt][2 * ksi][3]);
                    a[mt][2] = packh2(s[mt][2 * ksi + 1][0], s[mt][2 * ksi + 1][1]);
                    a[mt][3] = packh2(s[mt][2 * ksi + 1][2], s[mt][2 * ksi + 1][3]);
                }
                #pragma unroll
                for (int nt = 0; nt < 8; nt++) {
                    int vw = (q_ + nt * 8) * 68 + sub * 32 + ksi * 8 + c_;
                    uint32_t b0 = Vw[vw];
                    uint32_t b1 = Vw[vw + 4];
                    mma_f16(o[0][nt], a[0][0], a[0][1], a[0][2], a[0][3], b0, b1);
                    mma_f16(o[1][nt], a[1][0], a[1][1], a[1][2], a[1][3], b0, b1);
                }
            }
        }
        __syncthreads();
    }

    #pragma unroll
    for (int mt = 0; mt < 2; mt++) {
        #pragma unroll
        for (int half = 0; half < 2; half++) {
            l[mt][half] += __shfl_xor_sync(0xffffffffu, l[mt][half], 1);
            l[mt][half] += __shfl_xor_sync(0xffffffffu, l[mt][half], 2);
        }
    }

    #pragma unroll
    for (int mt = 0; mt < 2; mt++) {
        float inv0 = 1.0f / l[mt][0], inv1 = 1.0f / l[mt][1];
        int gr = bS + q0 + wq + mt * 16 + q_;
        #pragma unroll
        for (int nt = 0; nt < 8; nt++) {
            int col = h * DH + nt * 8 + 2 * c_;
            *(__half2*)&ctx[(size_t)gr * HID + col] =
                __floats2half2_rn(o[mt][nt][0] * inv0, o[mt][nt][1] * inv0);
            *(__half2*)&ctx[(size_t)(gr + 8) * HID + col] =
                __floats2half2_rn(o[mt][nt][2] * inv1, o[mt][nt][3] * inv1);
        }
    }
    #undef AFILL
}

// ---------------------------------------------------------------------------
extern "C" void kernel_launch(void* const* d_in, const int* in_sizes, int n_in,
                              void* d_out, int out_size)
{
    const float* hs   = (const float*)d_in[0];
    const float* mask = (const float*)d_in[1];
    const float* Wq   = (const float*)d_in[2];
    const float* bq   = (const float*)d_in[3];
    const float* Wk   = (const float*)d_in[4];
    const float* bk   = (const float*)d_in[5];
    const float* Wv   = (const float*)d_in[6];
    const float* bv   = (const float*)d_in[7];
    const float* Wo   = (const float*)d_in[8];
    const float* bo   = (const float*)d_in[9];
    float* out = (float*)d_out;

    __half *hsr, *wt, *qh, *kh, *vht, *cb;
    cudaGetSymbolAddress((void**)&hsr, g_hsr);
    cudaGetSymbolAddress((void**)&wt,  g_wt);
    cudaGetSymbolAddress((void**)&qh,  g_qh);
    cudaGetSymbolAddress((void**)&kh,  g_kh);
    cudaGetSymbolAddress((void**)&vht, g_vht);
    cudaGetSymbolAddress((void**)&cb,  g_ctx);

    cudaFuncSetAttribute(gemm9_qkv, cudaFuncAttributeMaxDynamicSharedMemorySize, G_SMEM_BYTES);
    cudaFuncSetAttribute(gemm9_o,   cudaFuncAttributeMaxDynamicSharedMemorySize, G_SMEM_BYTES);
    cudaFuncSetAttribute(attn7,     cudaFuncAttributeMaxDynamicSharedMemorySize, A_SMEM_BYTES);

    // --- pre-process: hs -> fp16; W -> transposed fp16 [n][k] ---
    round_hs_h<<<(MTOT * HID / 4 + 255) / 256, 256>>>(hs, hsr, MTOT * HID / 4);
    dim3 tgrid(HID / 32, HID / 32, 4);
    transpose_w_h<<<tgrid, dim3(32, 8)>>>(Wq, Wk, Wv, Wo, wt);

    // --- fused QKV projections (fp16 mma; fp16 head-major Q/K, transposed V) ---
    dim3 qkvgrid(HID / 128, MTOT / 128, 3);   // (6, 64, 3)
    gemm9_qkv<<<qkvgrid, 256, G_SMEM_BYTES>>>(hsr, wt, bq, bk, bv, qh, kh, vht);

    // --- attention (fp16 mma) ---
    dim3 agrid(SEQ / 128, NH, BATCH);    // (16, 12, 4) = 768 blocks
    attn7<<<agrid, 128, A_SMEM_BYTES>>>(qh, kh, vht, mask, cb);

    // --- output projection + GELU (fp16 mma, fp32 out) ---
    dim3 ggrid(HID / 128, MTOT / 128);   // (6, 64)
    gemm9_o<<<ggrid, 256, G_SMEM_BYTES>>>(cb, wt + 3 * (size_t)HID * HID, bo, out);
}

// round 13
// speedup vs baseline: 2.2373x; 1.1620x over previous
#include <cuda_runtime.h>
#include <cuda_fp16.h>
#include <math.h>
#include <stdint.h>

#define HID   768
#define NH    12
#define DH    64
#define BATCH 4
#define SEQ   2048
#define MTOT  (BATCH*SEQ)   // 8192

#define SCALE2 (0.125f * 1.44269504f)   // 1/sqrt(64) * log2(e), folded into Q
#define PEN2   (1e9f * 1.44269504f)

// Scratch (allocation-free rule: __device__ globals)
__device__ __half g_hsr[MTOT*HID];       // hs rounded to fp16
__device__ __half g_wt[4][HID*HID];      // W^T fp16: wt[n*HID+k] = (half)W[k*HID+n]
__device__ __half g_qh[MTOT*HID];        // q head-major fp16 [bh][s][d], pre-scaled by SCALE2
__device__ __half g_kh[MTOT*HID];        // k head-major fp16 [bh][s][d]
__device__ __half g_vht[MTOT*HID];       // v head-major TRANSPOSED fp16 [bh][d][s]
__device__ __half g_ctx[MTOT*HID];       // ctx standard layout fp16
__device__ int    g_mflag[BATCH];        // 1 if mask[b,:] is all ones

// ---------------------------------------------------------------------------
__device__ __forceinline__ float fexp2(float x) {
    float y;
    asm("ex2.approx.f32 %0, %1;" : "=f"(y) : "f"(x));
    return y;
}
__device__ __forceinline__ uint32_t h2exp2(uint32_t x) {
    uint32_t y;
    asm("ex2.approx.f16x2 %0, %1;" : "=r"(y) : "r"(x));
    return y;
}
__device__ __forceinline__ uint32_t packh2(float a, float b) {
    __half2 h = __floats2half2_rn(a, b);
    return *reinterpret_cast<uint32_t*>(&h);
}
__device__ __forceinline__ float2 h2f2(uint32_t x) {
    return __half22float2(*reinterpret_cast<__half2*>(&x));
}

// f16 inputs, f32 accumulators (PV + GEMMs)
__device__ __forceinline__ void mma_f16(float c[4],
    uint32_t a0, uint32_t a1, uint32_t a2, uint32_t a3,
    uint32_t b0, uint32_t b1)
{
    asm volatile(
        "mma.sync.aligned.m16n8k16.row.col.f32.f16.f16.f32 "
        "{%0,%1,%2,%3}, {%4,%5,%6,%7}, {%8,%9}, {%0,%1,%2,%3};"
        : "+f"(c[0]), "+f"(c[1]), "+f"(c[2]), "+f"(c[3])
        : "r"(a0), "r"(a1), "r"(a2), "r"(a3), "r"(b0), "r"(b1));
}
// f16 inputs AND f16 accumulators (QK scores) — C regs are packed f16x2
__device__ __forceinline__ void mma_f16c16(uint32_t c[2],
    uint32_t a0, uint32_t a1, uint32_t a2, uint32_t a3,
    uint32_t b0, uint32_t b1)
{
    asm volatile(
        "mma.sync.aligned.m16n8k16.row.col.f16.f16.f16.f16 "
        "{%0,%1}, {%2,%3,%4,%5}, {%6,%7}, {%0,%1};"
        : "+r"(c[0]), "+r"(c[1])
        : "r"(a0), "r"(a1), "r"(a2), "r"(a3), "r"(b0), "r"(b1));
}

__device__ __forceinline__ uint32_t smaddr(const void* p) {
    return (uint32_t)__cvta_generic_to_shared(p);
}
__device__ __forceinline__ void cpa16(uint32_t dst, const void* src) {
    asm volatile("cp.async.cg.shared.global [%0], [%1], 16;" :: "r"(dst), "l"(src));
}
__device__ __forceinline__ void cpa_commit() {
    asm volatile("cp.async.commit_group;" ::: "memory");
}
__device__ __forceinline__ void cpa_wait1() {
    asm volatile("cp.async.wait_group 1;" ::: "memory");
}

// ---------------------------------------------------------------------------
// Pre-processing
// ---------------------------------------------------------------------------
__global__ void round_hs_h(const float* __restrict__ in, __half* __restrict__ out, int n4)
{
    int i = blockIdx.x * blockDim.x + threadIdx.x;
    if (i < n4) {
        float4 v = ((const float4*)in)[i];
        ((uint2*)out)[i] = make_uint2(packh2(v.x, v.y), packh2(v.z, v.w));
    }
}
__global__ void transpose_w_h(const float* __restrict__ w0, const float* __restrict__ w1,
                              const float* __restrict__ w2, const float* __restrict__ w3,
                              __half* __restrict__ out)
{
    __shared__ float tile[32][33];
    const int wi = blockIdx.z;
    const float* src = wi == 0 ? w0 : (wi == 1 ? w1 : (wi == 2 ? w2 : w3));
    __half* dst = out + (size_t)wi * HID * HID;
    const int kb = blockIdx.y * 32, nb = blockIdx.x * 32;
    #pragma unroll
    for (int i = threadIdx.y; i < 32; i += 8)
        tile[i][threadIdx.x] = src[(size_t)(kb + i) * HID + nb + threadIdx.x];
    __syncthreads();
    #pragma unroll
    for (int i = threadIdx.y; i < 32; i += 8)
        dst[(size_t)(nb + i) * HID + kb + threadIdx.x] = __float2half_rn(tile[threadIdx.x][i]);
}
__global__ void mask_flags(const float* __restrict__ mask, int* __restrict__ flags)
{
    const int b = blockIdx.x;
    int ok = 1;
    for (int i = threadIdx.x; i < SEQ; i += blockDim.x)
        ok &= (mask[b * SEQ + i] == 1.0f);
    ok = __syncthreads_and(ok);
    if (threadIdx.x == 0) flags[b] = ok;
}

// ---------------------------------------------------------------------------
// fp16 GEMM: C = A[M,768] @ W + bias, A fp16 row-major, Wt fp16 [n][k].
// BM=128, BN=128, BK=64. 256 thr / 8 warps (4m x 2n), warp tile 32x64.
// mode 0: fp32 out + exact GELU; mode 1: fp16 head-major (scaled by oscale);
// mode 2: fp16 transposed [bh][d][s].
// ---------------------------------------------------------------------------
#define H_TS (128*72)
#define G_SMEM_BYTES (4*H_TS*2)       // 73728

__device__ __forceinline__ void gemm_body(
    const __half* __restrict__ A, const __half* __restrict__ Wt,
    const float* __restrict__ bias, float* __restrict__ Cf,
    __half* __restrict__ Ch, int mode, float oscale)
{
    extern __shared__ __half sh[];
    __half* Asm = sh;
    __half* Bsm = sh + 2 * H_TS;

    const int tid  = threadIdx.x;
    const int lane = tid & 31;
    const int warp = tid >> 5;
    const int wm   = (warp >> 1) * 32;
    const int wn   = (warp & 1) * 64;
    const int m0   = blockIdx.y * 128;
    const int n0   = blockIdx.x * 128;
    const int c_   = lane & 3;
    const int q_   = lane >> 2;

    float acc[2][8][4] = {};
    const int nT = HID / 64;   // 12

    #define GFILL(buf, k0_) do {                                              \
        const int _k0 = (k0_);                                                \
        __half* Ad = Asm + (buf) * H_TS;                                      \
        __half* Bd = Bsm + (buf) * H_TS;                                      \
        _Pragma("unroll")                                                     \
        for (int i = 0; i < 4; i++) {                                         \
            int idx = tid + i * 256;                                          \
            int row = idx >> 3, ch = idx & 7;                                 \
            cpa16(smaddr(Ad + row * 72 + ch * 8),                             \
                  A + (size_t)(m0 + row) * HID + _k0 + ch * 8);               \
            cpa16(smaddr(Bd + row * 72 + ch * 8),                             \
                  Wt + (size_t)(n0 + row) * HID + _k0 + ch * 8);              \
        }                                                                     \
    } while (0)

    GFILL(0, 0);
    cpa_commit();

    for (int t = 0; t < nT; t++) {
        const int cur = t & 1;
        if (t + 1 < nT) { GFILL(cur ^ 1, (t + 1) * 64); }
        cpa_commit();
        cpa_wait1();
        __syncthreads();

        const uint32_t* Aw = (const uint32_t*)(Asm + cur * H_TS);
        const uint32_t* Bw = (const uint32_t*)(Bsm + cur * H_TS);
        #pragma unroll
        for (int ksi = 0; ksi < 4; ksi++) {
            uint32_t a[2][4];
            #pragma unroll
            for (int mt = 0; mt < 2; mt++) {
                int r = wm + mt * 16 + q_;
                a[mt][0] = Aw[r * 36 + 8 * ksi + c_];
                a[mt][1] = Aw[(r + 8) * 36 + 8 * ksi + c_];
                a[mt][2] = Aw[r * 36 + 8 * ksi + c_ + 4];
                a[mt][3] = Aw[(r + 8) * 36 + 8 * ksi + c_ + 4];
            }
            #pragma unroll
            for (int nt = 0; nt < 8; nt++) {
                int n = wn + nt * 8 + q_;
                uint32_t b0 = Bw[n * 36 + 8 * ksi + c_];
                uint32_t b1 = Bw[n * 36 + 8 * ksi + c_ + 4];
                mma_f16(acc[0][nt], a[0][0], a[0][1], a[0][2], a[0][3], b0, b1);
                mma_f16(acc[1][nt], a[1][0], a[1][1], a[1][2], a[1][3], b0, b1);
            }
        }
        __syncthreads();
    }

    #pragma unroll
    for (int mt = 0; mt < 2; mt++) {
        int r0 = m0 + wm + mt * 16 + q_;
        int bb = r0 >> 11, s0 = r0 & 2047;
        #pragma unroll
        for (int nt = 0; nt < 8; nt++) {
            int col = n0 + wn + nt * 8 + 2 * c_;
            float bv0 = bias[col], bv1 = bias[col + 1];
            float v0 = acc[mt][nt][0] + bv0;
            float v1 = acc[mt][nt][1] + bv1;
            float v2 = acc[mt][nt][2] + bv0;
            float v3 = acc[mt][nt][3] + bv1;
            if (mode == 0) {
                v0 *= normcdff(v0); v1 *= normcdff(v1);
                v2 *= normcdff(v2); v3 *= normcdff(v3);
                *(float2*)&Cf[(size_t)r0       * HID + col] = make_float2(v0, v1);
                *(float2*)&Cf[(size_t)(r0 + 8) * HID + col] = make_float2(v2, v3);
            } else {
                int hh = col >> 6, d = col & 63;
                if (mode == 1) {
                    v0 *= oscale; v1 *= oscale; v2 *= oscale; v3 *= oscale;
                    __half* base = Ch + ((size_t)(bb * NH + hh) * SEQ) * 64;
                    *(__half2*)(base + (size_t)s0 * 64 + d)       = __floats2half2_rn(v0, v1);
                    *(__half2*)(base + (size_t)(s0 + 8) * 64 + d) = __floats2half2_rn(v2, v3);
                } else {
                    __half* base = Ch + ((size_t)(bb * NH + hh) * 64) * SEQ;
                    base[(size_t)d       * SEQ + s0]     = __float2half_rn(v0);
                    base[(size_t)(d + 1) * SEQ + s0]     = __float2half_rn(v1);
                    base[(size_t)d       * SEQ + s0 + 8] = __float2half_rn(v2);
                    base[(size_t)(d + 1) * SEQ + s0 + 8] = __float2half_rn(v3);
                }
            }
        }
    }
    #undef GFILL
}

__global__ __launch_bounds__(256, 2) void gemm9_qkv(
    const __half* __restrict__ A, const __half* __restrict__ Wt,
    const float* __restrict__ b0, const float* __restrict__ b1, const float* __restrict__ b2,
    __half* __restrict__ qh, __half* __restrict__ kh, __half* __restrict__ vht)
{
    const int z = blockIdx.z;
    const __half* W = Wt + (size_t)z * HID * HID;
    const float* bb = z == 0 ? b0 : (z == 1 ? b1 : b2);
    __half* Ch = z == 0 ? qh : (z == 1 ? kh : vht);
    gemm_body(A, W, bb, nullptr, Ch, z == 2 ? 2 : 1, z == 0 ? SCALE2 : 1.0f);
}

__global__ __launch_bounds__(256, 2) void gemm9_o(
    const __half* __restrict__ A, const __half* __restrict__ Wt,
    const float* __restrict__ bias, float* __restrict__ C)
{
    gemm_body(A, Wt, bias, C, nullptr, 0, 1.0f);
}

// ---------------------------------------------------------------------------
// Flash attention: fp16 QK with f16 accumulators (C-regs double as PV
// A-fragments — zero packing), exp via ex2.approx.f16x2 on the fast path,
// all-ones-mask fast path (CTA-uniform branch). Q pre-scaled by SCALE2.
// Block = (b, h, 128-q-tile), 128 thr / 4 warps, warp = 32 q-rows, 2 CTA/SM.
// Smem: K[2][128][72h] + V[2][64][136h] + ms[2][128]f = 72704 B.
// ---------------------------------------------------------------------------
#define TSK 128
#define K_ROWB 144
#define V_ROWB 272
#define KBUF_B (128*K_ROWB)
#define VBUF_B (64*V_ROWB)
#define AV_OFF (2*KBUF_B)
#define AM_OFF (AV_OFF + 2*VBUF_B)
#define A_SMEM_BYTES (AM_OFF + 2*TSK*4)

__global__ __launch_bounds__(128, 2) void attn8(
    const __half* __restrict__ qh, const __half* __restrict__ kh,
    const __half* __restrict__ vht, const float* __restrict__ mask,
    const int* __restrict__ mflag, __half* __restrict__ ctx)
{
    extern __shared__ char smc[];
    float* msb = (float*)(smc + AM_OFF);

    const int tid  = threadIdx.x;
    const int lane = tid & 31;
    const int warp = tid >> 5;
    const int c_   = lane & 3;
    const int q_   = lane >> 2;
    const int b    = blockIdx.z;
    const int h    = blockIdx.y;
    const int q0   = blockIdx.x * 128;
    const int bS   = b * SEQ;
    const int bh   = b * NH + h;
    const int wq   = warp * 32;

    const bool fast = (mflag[b] != 0);

    const __half* kbase = kh  + (size_t)bh * SEQ * 64;
    const __half* vbase = vht + (size_t)bh * 64 * SEQ;

    #define AFILL(buf, k0_) do {                                               \
        const int _k0 = (k0_);                                                 \
        char* Kd = smc + (buf) * KBUF_B;                                       \
        char* Vd = smc + AV_OFF + (buf) * VBUF_B;                              \
        _Pragma("unroll")                                                      \
        for (int i = 0; i < 8; i++) {                                          \
            int idx = tid + i * 128;                                           \
            int kr = idx >> 3, ch = idx & 7;                                   \
            cpa16(smaddr(Kd + kr * K_ROWB + ch * 16),                          \
                  kbase + ((size_t)(_k0 + kr)) * 64 + ch * 8);                 \
            int vr = idx >> 4, vch = idx & 15;                                 \
            cpa16(smaddr(Vd + vr * V_ROWB + vch * 16),                         \
                  vbase + (size_t)vr * SEQ + _k0 + vch * 8);                   \
        }                                                                      \
        if (tid < 32) cpa16(smaddr((char*)(msb + (buf) * TSK) + tid * 16),     \
                            mask + bS + _k0 + tid * 4);                        \
    } while (0)

    AFILL(0, 0);
    cpa_commit();

    uint32_t qa[2][4][4];
    #pragma unroll
    for (int mt = 0; mt < 2; mt++) {
        const __half* p0 = qh + ((size_t)bh * SEQ + q0 + wq + mt * 16 + q_) * 64;
        const __half* p1 = p0 + 8 * 64;
        #pragma unroll
        for (int ksi = 0; ksi < 4; ksi++) {
            qa[mt][ksi][0] = *(const uint32_t*)(p0 + 16 * ksi + 2 * c_);
            qa[mt][ksi][1] = *(const uint32_t*)(p1 + 16 * ksi + 2 * c_);
            qa[mt][ksi][2] = *(const uint32_t*)(p0 + 16 * ksi + 2 * c_ + 8);
            qa[mt][ksi][3] = *(const uint32_t*)(p1 + 16 * ksi + 2 * c_ + 8);
        }
    }

    float mq[2][2];
    #pragma unroll
    for (int mt = 0; mt < 2; mt++) {
        mq[mt][0] = mask[bS + q0 + wq + mt * 16 + q_];
        mq[mt][1] = mask[bS + q0 + wq + mt * 16 + q_ + 8];
    }

    float l[2][2] = {};
    float o[2][8][4] = {};

    const int nT = SEQ / TSK;   // 16
    for (int t = 0; t < nT; t++) {
        const int cur = t & 1;
        if (t + 1 < nT) { AFILL(cur ^ 1, (t + 1) * TSK); }
        cpa_commit();
        cpa_wait1();
        __syncthreads();

        const uint32_t* Kw = (const uint32_t*)(smc + cur * KBUF_B);
        const uint32_t* Vw = (const uint32_t*)(smc + AV_OFF + cur * VBUF_B);
        const float* mc = msb + cur * TSK;

        #pragma unroll
        for (int sub = 0; sub < 2; sub++) {
            // ---- S' = (Q*scale) K^T, f16 accumulators (packed C-regs)
            uint32_t sP[2][8][2] = {};
            #pragma unroll
            for (int ksi = 0; ksi < 4; ksi++) {
                #pragma unroll
                for (int nt = 0; nt < 8; nt++) {
                    int kw = (sub * 64 + nt * 8 + q_) * 36 + ksi * 8 + c_;
                    uint32_t b0 = Kw[kw];
                    uint32_t b1 = Kw[kw + 4];
                    mma_f16c16(sP[0][nt], qa[0][ksi][0], qa[0][ksi][1], qa[0][ksi][2], qa[0][ksi][3], b0, b1);
                    mma_f16c16(sP[1][nt], qa[1][ksi][0], qa[1][ksi][1], qa[1][ksi][2], qa[1][ksi][3], b0, b1);
                }
            }

            // ---- exp (+ mask on slow path), accumulate row sums in fp32
            if (fast) {
                #pragma unroll
                for (int mt = 0; mt < 2; mt++) {
                    #pragma unroll
                    for (int nt = 0; nt < 8; nt++) {
                        sP[mt][nt][0] = h2exp2(sP[mt][nt][0]);
                        sP[mt][nt][1] = h2exp2(sP[mt][nt][1]);
                        float2 p0 = h2f2(sP[mt][nt][0]);
                        float2 p1 = h2f2(sP[mt][nt][1]);
                        l[mt][0] += p0.x + p0.y;
                        l[mt][1] += p1.x + p1.y;
                    }
                }
            } else {
                #pragma unroll
                for (int mt = 0; mt < 2; mt++) {
                    #pragma unroll
                    for (int nt = 0; nt < 8; nt++) {
                        float mk0 = mc[sub * 64 + nt * 8 + 2 * c_];
                        float mk1 = mc[sub * 64 + nt * 8 + 2 * c_ + 1];
                        float2 f0 = h2f2(sP[mt][nt][0]);
                        float2 f1 = h2f2(sP[mt][nt][1]);
                        float e;
                        e = mq[mt][0] * mk0; f0.x = fexp2(e * f0.x - (1.0f - e) * PEN2);
                        e = mq[mt][0] * mk1; f0.y = fexp2(e * f0.y - (1.0f - e) * PEN2);
                        e = mq[mt][1] * mk0; f1.x = fexp2(e * f1.x - (1.0f - e) * PEN2);
                        e = mq[mt][1] * mk1; f1.y = fexp2(e * f1.y - (1.0f - e) * PEN2);
                        l[mt][0] += f0.x + f0.y;
                        l[mt][1] += f1.x + f1.y;
                        sP[mt][nt][0] = packh2(f0.x, f0.y);
                        sP[mt][nt][1] = packh2(f1.x, f1.y);
                    }
                }
            }

            // ---- O += P V: C-regs ARE the A-fragments (no packing)
            #pragma unroll
            for (int ksi = 0; ksi < 4; ksi++) {
                #pragma unroll
                for (int nt = 0; nt < 8; nt++) {
                    int vw = (q_ + nt * 8) * 68 + sub * 32 + ksi * 8 + c_;
                    uint32_t b0 = Vw[vw];
                    uint32_t b1 = Vw[vw + 4];
                    mma_f16(o[0][nt], sP[0][2*ksi][0], sP[0][2*ksi][1],
                            sP[0][2*ksi+1][0], sP[0][2*ksi+1][1], b0, b1);
                    mma_f16(o[1][nt], sP[1][2*ksi][0], sP[1][2*ksi][1],
                            sP[1][2*ksi+1][0], sP[1][2*ksi+1][1], b0, b1);
                }
            }
        }
        __syncthreads();
    }

    // ---- final row-sum reduction over 4-lane group, normalize, write
    #pragma unroll
    for (int mt = 0; mt < 2; mt++) {
        #pragma unroll
        for (int half = 0; half < 2; half++) {
            l[mt][half] += __shfl_xor_sync(0xffffffffu, l[mt][half], 1);
            l[mt][half] += __shfl_xor_sync(0xffffffffu, l[mt][half], 2);
        }
    }

    #pragma unroll
    for (int mt = 0; mt < 2; mt++) {
        float inv0 = 1.0f / l[mt][0], inv1 = 1.0f / l[mt][1];
        int gr = bS + q0 + wq + mt * 16 + q_;
        #pragma unroll
        for (int nt = 0; nt < 8; nt++) {
            int col = h * DH + nt * 8 + 2 * c_;
            *(__half2*)&ctx[(size_t)gr * HID + col] =
                __floats2half2_rn(o[mt][nt][0] * inv0, o[mt][nt][1] * inv0);
            *(__half2*)&ctx[(size_t)(gr + 8) * HID + col] =
                __floats2half2_rn(o[mt][nt][2] * inv1, o[mt][nt][3] * inv1);
        }
    }
    #undef AFILL
}

// ---------------------------------------------------------------------------
extern "C" void kernel_launch(void* const* d_in, const int* in_sizes, int n_in,
                              void* d_out, int out_size)
{
    const float* hs   = (const float*)d_in[0];
    const float* mask = (const float*)d_in[1];
    const float* Wq   = (const float*)d_in[2];
    const float* bq   = (const float*)d_in[3];
    const float* Wk   = (const float*)d_in[4];
    const float* bk   = (const float*)d_in[5];
    const float* Wv   = (const float*)d_in[6];
    const float* bv   = (const float*)d_in[7];
    const float* Wo   = (const float*)d_in[8];
    const float* bo   = (const float*)d_in[9];
    float* out = (float*)d_out;

    __half *hsr, *wt, *qh, *kh, *vht, *cb;
    int* mfl;
    cudaGetSymbolAddress((void**)&hsr, g_hsr);
    cudaGetSymbolAddress((void**)&wt,  g_wt);
    cudaGetSymbolAddress((void**)&qh,  g_qh);
    cudaGetSymbolAddress((void**)&kh,  g_kh);
    cudaGetSymbolAddress((void**)&vht, g_vht);
    cudaGetSymbolAddress((void**)&cb,  g_ctx);
    cudaGetSymbolAddress((void**)&mfl, g_mflag);

    cudaFuncSetAttribute(gemm9_qkv, cudaFuncAttributeMaxDynamicSharedMemorySize, G_SMEM_BYTES);
    cudaFuncSetAttribute(gemm9_o,   cudaFuncAttributeMaxDynamicSharedMemorySize, G_SMEM_BYTES);
    cudaFuncSetAttribute(attn8,     cudaFuncAttributeMaxDynamicSharedMemorySize, A_SMEM_BYTES);

    // --- pre-process: hs -> fp16; W -> transposed fp16; mask flags ---
    round_hs_h<<<(MTOT * HID / 4 + 255) / 256, 256>>>(hs, hsr, MTOT * HID / 4);
    dim3 tgrid(HID / 32, HID / 32, 4);
    transpose_w_h<<<tgrid, dim3(32, 8)>>>(Wq, Wk, Wv, Wo, wt);
    mask_flags<<<BATCH, 256>>>(mask, mfl);

    // --- fused QKV projections (Q pre-scaled by SCALE2) ---
    dim3 qkvgrid(HID / 128, MTOT / 128, 3);   // (6, 64, 3)
    gemm9_qkv<<<qkvgrid, 256, G_SMEM_BYTES>>>(hsr, wt, bq, bk, bv, qh, kh, vht);

    // --- attention ---
    dim3 agrid(SEQ / 128, NH, BATCH);    // (16, 12, 4) = 768 blocks
    attn8<<<agrid, 128, A_SMEM_BYTES>>>(qh, kh, vht, mask, mfl, cb);

    // --- output projection + GELU ---
    dim3 ggrid(HID / 128, MTOT / 128);   // (6, 64)
    gemm9_o<<<ggrid, 256, G_SMEM_BYTES>>>(cb, wt + 3 * (size_t)HID * HID, bo, out);
}

// round 14
// speedup vs baseline: 2.2543x; 1.0076x over previous
#include <cuda_runtime.h>
#include <cuda_fp16.h>
#include <math.h>
#include <stdint.h>

#define HID   768
#define NH    12
#define DH    64
#define BATCH 4
#define SEQ   2048
#define MTOT  (BATCH*SEQ)   // 8192

#define SCALE2 (0.125f * 1.44269504f)   // 1/sqrt(64) * log2(e), folded into Q
#define PEN2   (1e9f * 1.44269504f)

// Scratch (allocation-free rule: __device__ globals)
__device__ __half g_hsr[MTOT*HID];       // hs rounded to fp16
__device__ __half g_wt[4][HID*HID];      // W^T fp16: wt[n*HID+k] = (half)W[k*HID+n]
__device__ __half g_qh[MTOT*HID];        // q head-major fp16 [bh][s][d], pre-scaled by SCALE2
__device__ __half g_kh[MTOT*HID];        // k head-major fp16 [bh][s][d]
__device__ __half g_vht[MTOT*HID];       // v head-major TRANSPOSED fp16 [bh][d][s]
__device__ __half g_ctx[MTOT*HID];       // ctx standard layout fp16
__device__ int    g_mflag[BATCH];        // 1 if mask[b,:] is all ones

// ---------------------------------------------------------------------------
__device__ __forceinline__ float fexp2(float x) {
    float y;
    asm("ex2.approx.f32 %0, %1;" : "=f"(y) : "f"(x));
    return y;
}
__device__ __forceinline__ uint32_t h2exp2(uint32_t x) {
    uint32_t y;
    asm("ex2.approx.f16x2 %0, %1;" : "=r"(y) : "r"(x));
    return y;
}
__device__ __forceinline__ uint32_t packh2(float a, float b) {
    __half2 h = __floats2half2_rn(a, b);
    return *reinterpret_cast<uint32_t*>(&h);
}
__device__ __forceinline__ float2 h2f2(uint32_t x) {
    return __half22float2(*reinterpret_cast<__half2*>(&x));
}

// f16 inputs, f32 accumulators (PV + GEMMs)
__device__ __forceinline__ void mma_f16(float c[4],
    uint32_t a0, uint32_t a1, uint32_t a2, uint32_t a3,
    uint32_t b0, uint32_t b1)
{
    asm volatile(
        "mma.sync.aligned.m16n8k16.row.col.f32.f16.f16.f32 "
        "{%0,%1,%2,%3}, {%4,%5,%6,%7}, {%8,%9}, {%0,%1,%2,%3};"
        : "+f"(c[0]), "+f"(c[1]), "+f"(c[2]), "+f"(c[3])
        : "r"(a0), "r"(a1), "r"(a2), "r"(a3), "r"(b0), "r"(b1));
}
// f16 inputs AND f16 accumulators (QK scores) — C regs are packed f16x2
__device__ __forceinline__ void mma_f16c16(uint32_t c[2],
    uint32_t a0, uint32_t a1, uint32_t a2, uint32_t a3,
    uint32_t b0, uint32_t b1)
{
    asm volatile(
        "mma.sync.aligned.m16n8k16.row.col.f16.f16.f16.f16 "
        "{%0,%1}, {%2,%3,%4,%5}, {%6,%7}, {%0,%1};"
        : "+r"(c[0]), "+r"(c[1])
        : "r"(a0), "r"(a1), "r"(a2), "r"(a3), "r"(b0), "r"(b1));
}
// ldmatrix x4: 4 8x8 b16 matrices; lane L supplies row address
__device__ __forceinline__ void ldsm_x4(uint32_t r[4], uint32_t addr)
{
    asm volatile(
        "ldmatrix.sync.aligned.m8n8.x4.shared.b16 {%0,%1,%2,%3}, [%4];"
        : "=r"(r[0]), "=r"(r[1]), "=r"(r[2]), "=r"(r[3]) : "r"(addr));
}

__device__ __forceinline__ uint32_t smaddr(const void* p) {
    return (uint32_t)__cvta_generic_to_shared(p);
}
__device__ __forceinline__ void cpa16(uint32_t dst, const void* src) {
    asm volatile("cp.async.cg.shared.global [%0], [%1], 16;" :: "r"(dst), "l"(src));
}
__device__ __forceinline__ void cpa_commit() {
    asm volatile("cp.async.commit_group;" ::: "memory");
}
__device__ __forceinline__ void cpa_wait1() {
    asm volatile("cp.async.wait_group 1;" ::: "memory");
}

// ---------------------------------------------------------------------------
// Pre-processing
// ---------------------------------------------------------------------------
__global__ void round_hs_h(const float* __restrict__ in, __half* __restrict__ out, int n4)
{
    int i = blockIdx.x * blockDim.x + threadIdx.x;
    if (i < n4) {
        float4 v = ((const float4*)in)[i];
        ((uint2*)out)[i] = make_uint2(packh2(v.x, v.y), packh2(v.z, v.w));
    }
}
__global__ void transpose_w_h(const float* __restrict__ w0, const float* __restrict__ w1,
                              const float* __restrict__ w2, const float* __restrict__ w3,
                              __half* __restrict__ out)
{
    __shared__ float tile[32][33];
    const int wi = blockIdx.z;
    const float* src = wi == 0 ? w0 : (wi == 1 ? w1 : (wi == 2 ? w2 : w3));
    __half* dst = out + (size_t)wi * HID * HID;
    const int kb = blockIdx.y * 32, nb = blockIdx.x * 32;
    #pragma unroll
    for (int i = threadIdx.y; i < 32; i += 8)
        tile[i][threadIdx.x] = src[(size_t)(kb + i) * HID + nb + threadIdx.x];
    __syncthreads();
    #pragma unroll
    for (int i = threadIdx.y; i < 32; i += 8)
        dst[(size_t)(nb + i) * HID + kb + threadIdx.x] = __float2half_rn(tile[threadIdx.x][i]);
}
__global__ void mask_flags(const float* __restrict__ mask, int* __restrict__ flags)
{
    const int b = blockIdx.x;
    int ok = 1;
    for (int i = threadIdx.x; i < SEQ; i += blockDim.x)
        ok &= (mask[b * SEQ + i] == 1.0f);
    ok = __syncthreads_and(ok);
    if (threadIdx.x == 0) flags[b] = ok;
}

// ---------------------------------------------------------------------------
// fp16 GEMM with ldmatrix fragment loads.
// BM=128, BN=128, BK=64. 256 thr / 8 warps (4m x 2n), warp tile 32x64.
// Smem: As[2][128][72h]+Bs[2][128][72h]=73728B, 2 CTA/SM.
// ---------------------------------------------------------------------------
#define H_TS (128*72)
#define G_SMEM_BYTES (4*H_TS*2)       // 73728

__device__ __forceinline__ void gemm_body(
    const __half* __restrict__ A, const __half* __restrict__ Wt,
    const float* __restrict__ bias, float* __restrict__ Cf,
    __half* __restrict__ Ch, int mode, float oscale)
{
    extern __shared__ __half sh[];
    __half* Asm = sh;
    __half* Bsm = sh + 2 * H_TS;

    const int tid  = threadIdx.x;
    const int lane = tid & 31;
    const int warp = tid >> 5;
    const int wm   = (warp >> 1) * 32;
    const int wn   = (warp & 1) * 64;
    const int m0   = blockIdx.y * 128;
    const int n0   = blockIdx.x * 128;
    const int c_   = lane & 3;
    const int q_   = lane >> 2;

    // ldmatrix lane addressing: row = base + (lane&15), k-half-off = (lane>>4)*8
    const int lrow = lane & 15;
    const int lkoh = ((lane >> 4) & 1) * 8;
    const uint32_t a_lane_off = (uint32_t)(((wm + lrow) * 72 + lkoh) * 2);
    const uint32_t b_lane_off = (uint32_t)(((wn + lrow) * 72 + lkoh) * 2);

    float acc[2][8][4] = {};
    const int nT = HID / 64;   // 12

    #define GFILL(buf, k0_) do {                                              \
        const int _k0 = (k0_);                                                \
        __half* Ad = Asm + (buf) * H_TS;                                      \
        __half* Bd = Bsm + (buf) * H_TS;                                      \
        _Pragma("unroll")                                                     \
        for (int i = 0; i < 4; i++) {                                         \
            int idx = tid + i * 256;                                          \
            int row = idx >> 3, ch = idx & 7;                                 \
            cpa16(smaddr(Ad + row * 72 + ch * 8),                             \
                  A + (size_t)(m0 + row) * HID + _k0 + ch * 8);               \
            cpa16(smaddr(Bd + row * 72 + ch * 8),                             \
                  Wt + (size_t)(n0 + row) * HID + _k0 + ch * 8);              \
        }                                                                     \
    } while (0)

    GFILL(0, 0);
    cpa_commit();

    for (int t = 0; t < nT; t++) {
        const int cur = t & 1;
        if (t + 1 < nT) { GFILL(cur ^ 1, (t + 1) * 64); }
        cpa_commit();
        cpa_wait1();
        __syncthreads();

        const uint32_t abase = smaddr(Asm + cur * H_TS) + a_lane_off;
        const uint32_t bbase = smaddr(Bsm + cur * H_TS) + b_lane_off;
        #pragma unroll
        for (int ksi = 0; ksi < 4; ksi++) {
            uint32_t a[2][4];
            ldsm_x4(a[0], abase + ksi * 32);                 // +16 halves/ksi
            ldsm_x4(a[1], abase + 16 * 144 + ksi * 32);      // +16 rows
            #pragma unroll
            for (int ntp = 0; ntp < 4; ntp++) {
                uint32_t bf[4];                               // b0[2p], b0[2p+1], b1[2p], b1[2p+1]
                ldsm_x4(bf, bbase + ntp * 16 * 144 + ksi * 32);
                mma_f16(acc[0][2*ntp],   a[0][0], a[0][1], a[0][2], a[0][3], bf[0], bf[2]);
                mma_f16(acc[0][2*ntp+1], a[0][0], a[0][1], a[0][2], a[0][3], bf[1], bf[3]);
                mma_f16(acc[1][2*ntp],   a[1][0], a[1][1], a[1][2], a[1][3], bf[0], bf[2]);
                mma_f16(acc[1][2*ntp+1], a[1][0], a[1][1], a[1][2], a[1][3], bf[1], bf[3]);
            }
        }
        __syncthreads();
    }

    #pragma unroll
    for (int mt = 0; mt < 2; mt++) {
        int r0 = m0 + wm + mt * 16 + q_;
        int bb = r0 >> 11, s0 = r0 & 2047;
        #pragma unroll
        for (int nt = 0; nt < 8; nt++) {
            int col = n0 + wn + nt * 8 + 2 * c_;
            float bv0 = bias[col], bv1 = bias[col + 1];
            float v0 = acc[mt][nt][0] + bv0;
            float v1 = acc[mt][nt][1] + bv1;
            float v2 = acc[mt][nt][2] + bv0;
            float v3 = acc[mt][nt][3] + bv1;
            if (mode == 0) {
                v0 *= normcdff(v0); v1 *= normcdff(v1);
                v2 *= normcdff(v2); v3 *= normcdff(v3);
                *(float2*)&Cf[(size_t)r0       * HID + col] = make_float2(v0, v1);
                *(float2*)&Cf[(size_t)(r0 + 8) * HID + col] = make_float2(v2, v3);
            } else {
                int hh = col >> 6, d = col & 63;
                if (mode == 1) {
                    v0 *= oscale; v1 *= oscale; v2 *= oscale; v3 *= oscale;
                    __half* base = Ch + ((size_t)(bb * NH + hh) * SEQ) * 64;
                    *(__half2*)(base + (size_t)s0 * 64 + d)       = __floats2half2_rn(v0, v1);
                    *(__half2*)(base + (size_t)(s0 + 8) * 64 + d) = __floats2half2_rn(v2, v3);
                } else {
                    __half* base = Ch + ((size_t)(bb * NH + hh) * 64) * SEQ;
                    base[(size_t)d       * SEQ + s0]     = __float2half_rn(v0);
                    base[(size_t)(d + 1) * SEQ + s0]     = __float2half_rn(v1);
                    base[(size_t)d       * SEQ + s0 + 8] = __float2half_rn(v2);
                    base[(size_t)(d + 1) * SEQ + s0 + 8] = __float2half_rn(v3);
                }
            }
        }
    }
    #undef GFILL
}

__global__ __launch_bounds__(256, 2) void gemm10_qkv(
    const __half* __restrict__ A, const __half* __restrict__ Wt,
    const float* __restrict__ b0, const float* __restrict__ b1, const float* __restrict__ b2,
    __half* __restrict__ qh, __half* __restrict__ kh, __half* __restrict__ vht)
{
    const int z = blockIdx.z;
    const __half* W = Wt + (size_t)z * HID * HID;
    const float* bb = z == 0 ? b0 : (z == 1 ? b1 : b2);
    __half* Ch = z == 0 ? qh : (z == 1 ? kh : vht);
    gemm_body(A, W, bb, nullptr, Ch, z == 2 ? 2 : 1, z == 0 ? SCALE2 : 1.0f);
}

__global__ __launch_bounds__(256, 2) void gemm10_o(
    const __half* __restrict__ A, const __half* __restrict__ Wt,
    const float* __restrict__ bias, float* __restrict__ C)
{
    gemm_body(A, Wt, bias, C, nullptr, 0, 1.0f);
}

// ---------------------------------------------------------------------------
// Flash attention (R13 attn8), now 3 CTA/SM (12 warps/SM).
// Smem: K[2][128][72h] + V[2][64][136h] + ms[2][128]f = 72704 B.
// ---------------------------------------------------------------------------
#define TSK 128
#define K_ROWB 144
#define V_ROWB 272
#define KBUF_B (128*K_ROWB)
#define VBUF_B (64*V_ROWB)
#define AV_OFF (2*KBUF_B)
#define AM_OFF (AV_OFF + 2*VBUF_B)
#define A_SMEM_BYTES (AM_OFF + 2*TSK*4)

__global__ __launch_bounds__(128, 3) void attn8(
    const __half* __restrict__ qh, const __half* __restrict__ kh,
    const __half* __restrict__ vht, const float* __restrict__ mask,
    const int* __restrict__ mflag, __half* __restrict__ ctx)
{
    extern __shared__ char smc[];
    float* msb = (float*)(smc + AM_OFF);

    const int tid  = threadIdx.x;
    const int lane = tid & 31;
    const int warp = tid >> 5;
    const int c_   = lane & 3;
    const int q_   = lane >> 2;
    const int b    = blockIdx.z;
    const int h    = blockIdx.y;
    const int q0   = blockIdx.x * 128;
    const int bS   = b * SEQ;
    const int bh   = b * NH + h;
    const int wq   = warp * 32;

    const bool fast = (mflag[b] != 0);

    const __half* kbase = kh  + (size_t)bh * SEQ * 64;
    const __half* vbase = vht + (size_t)bh * 64 * SEQ;

    #define AFILL(buf, k0_) do {                                               \
        const int _k0 = (k0_);                                                 \
        char* Kd = smc + (buf) * KBUF_B;                                       \
        char* Vd = smc + AV_OFF + (buf) * VBUF_B;                              \
        _Pragma("unroll")                                                      \
        for (int i = 0; i < 8; i++) {                                          \
            int idx = tid + i * 128;                                           \
            int kr = idx >> 3, ch = idx & 7;                                   \
            cpa16(smaddr(Kd + kr * K_ROWB + ch * 16),                          \
                  kbase + ((size_t)(_k0 + kr)) * 64 + ch * 8);                 \
            int vr = idx >> 4, vch = idx & 15;                                 \
            cpa16(smaddr(Vd + vr * V_ROWB + vch * 16),                         \
                  vbase + (size_t)vr * SEQ + _k0 + vch * 8);                   \
        }                                                                      \
        if (tid < 32) cpa16(smaddr((char*)(msb + (buf) * TSK) + tid * 16),     \
                            mask + bS + _k0 + tid * 4);                        \
    } while (0)

    AFILL(0, 0);
    cpa_commit();

    uint32_t qa[2][4][4];
    #pragma unroll
    for (int mt = 0; mt < 2; mt++) {
        const __half* p0 = qh + ((size_t)bh * SEQ + q0 + wq + mt * 16 + q_) * 64;
        const __half* p1 = p0 + 8 * 64;
        #pragma unroll
        for (int ksi = 0; ksi < 4; ksi++) {
            qa[mt][ksi][0] = *(const uint32_t*)(p0 + 16 * ksi + 2 * c_);
            qa[mt][ksi][1] = *(const uint32_t*)(p1 + 16 * ksi + 2 * c_);
            qa[mt][ksi][2] = *(const uint32_t*)(p0 + 16 * ksi + 2 * c_ + 8);
            qa[mt][ksi][3] = *(const uint32_t*)(p1 + 16 * ksi + 2 * c_ + 8);
        }
    }

    float mq[2][2];
    #pragma unroll
    for (int mt = 0; mt < 2; mt++) {
        mq[mt][0] = mask[bS + q0 + wq + mt * 16 + q_];
        mq[mt][1] = mask[bS + q0 + wq + mt * 16 + q_ + 8];
    }

    float l[2][2] = {};
    float o[2][8][4] = {};

    const int nT = SEQ / TSK;   // 16
    for (int t = 0; t < nT; t++) {
        const int cur = t & 1;
        if (t + 1 < nT) { AFILL(cur ^ 1, (t + 1) * TSK); }
        cpa_commit();
        cpa_wait1();
        __syncthreads();

        const uint32_t* Kw = (const uint32_t*)(smc + cur * KBUF_B);
        const uint32_t* Vw = (const uint32_t*)(smc + AV_OFF + cur * VBUF_B);
        const float* mc = msb + cur * TSK;

        #pragma unroll
        for (int sub = 0; sub < 2; sub++) {
            // ---- S' = (Q*scale) K^T, f16 accumulators (packed C-regs)
            uint32_t sP[2][8][2] = {};
            #pragma unroll
            for (int ksi = 0; ksi < 4; ksi++) {
                #pragma unroll
                for (int nt = 0; nt < 8; nt++) {
                    int kw = (sub * 64 + nt * 8 + q_) * 36 + ksi * 8 + c_;
                    uint32_t b0 = Kw[kw];
                    uint32_t b1 = Kw[kw + 4];
                    mma_f16c16(sP[0][nt], qa[0][ksi][0], qa[0][ksi][1], qa[0][ksi][2], qa[0][ksi][3], b0, b1);
                    mma_f16c16(sP[1][nt], qa[1][ksi][0], qa[1][ksi][1], qa[1][ksi][2], qa[1][ksi][3], b0, b1);
                }
            }

            // ---- exp (+ mask on slow path), accumulate row sums in fp32
            if (fast) {
                #pragma unroll
                for (int mt = 0; mt < 2; mt++) {
                    #pragma unroll
                    for (int nt = 0; nt < 8; nt++) {
                        sP[mt][nt][0] = h2exp2(sP[mt][nt][0]);
                        sP[mt][nt][1] = h2exp2(sP[mt][nt][1]);
                        float2 p0 = h2f2(sP[mt][nt][0]);
                        float2 p1 = h2f2(sP[mt][nt][1]);
                        l[mt][0] += p0.x + p0.y;
                        l[mt][1] += p1.x + p1.y;
                    }
                }
            } else {
                #pragma unroll
                for (int mt = 0; mt < 2; mt++) {
                    #pragma unroll
                    for (int nt = 0; nt < 8; nt++) {
                        float mk0 = mc[sub * 64 + nt * 8 + 2 * c_];
                        float mk1 = mc[sub * 64 + nt * 8 + 2 * c_ + 1];
                        float2 f0 = h2f2(sP[mt][nt][0]);
                        float2 f1 = h2f2(sP[mt][nt][1]);
                        float e;
                        e = mq[mt][0] * mk0; f0.x = fexp2(e * f0.x - (1.0f - e) * PEN2);
                        e = mq[mt][0] * mk1; f0.y = fexp2(e * f0.y - (1.0f - e) * PEN2);
                        e = mq[mt][1] * mk0; f1.x = fexp2(e * f1.x - (1.0f - e) * PEN2);
                        e = mq[mt][1] * mk1; f1.y = fexp2(e * f1.y - (1.0f - e) * PEN2);
                        l[mt][0] += f0.x + f0.y;
                        l[mt][1] += f1.x + f1.y;
                        sP[mt][nt][0] = packh2(f0.x, f0.y);
                        sP[mt][nt][1] = packh2(f1.x, f1.y);
                    }
                }
            }

            // ---- O += P V: C-regs ARE the A-fragments (no packing)
            #pragma unroll
            for (int ksi = 0; ksi < 4; ksi++) {
                #pragma unroll
                for (int nt = 0; nt < 8; nt++) {
                    int vw = (q_ + nt * 8) * 68 + sub * 32 + ksi * 8 + c_;
                    uint32_t b0 = Vw[vw];
                    uint32_t b1 = Vw[vw + 4];
                    mma_f16(o[0][nt], sP[0][2*ksi][0], sP[0][2*ksi][1],
                            sP[0][2*ksi+1][0], sP[0][2*ksi+1][1], b0, b1);
                    mma_f16(o[1][nt], sP[1][2*ksi][0], sP[1][2*ksi][1],
                            sP[1][2*ksi+1][0], sP[1][2*ksi+1][1], b0, b1);
                }
            }
        }
        __syncthreads();
    }

    // ---- final row-sum reduction over 4-lane group, normalize, write
    #pragma unroll
    for (int mt = 0; mt < 2; mt++) {
        #pragma unroll
        for (int half = 0; half < 2; half++) {
            l[mt][half] += __shfl_xor_sync(0xffffffffu, l[mt][half], 1);
            l[mt][half] += __shfl_xor_sync(0xffffffffu, l[mt][half], 2);
        }
    }

    #pragma unroll
    for (int mt = 0; mt < 2; mt++) {
        float inv0 = 1.0f / l[mt][0], inv1 = 1.0f / l[mt][1];
        int gr = bS + q0 + wq + mt * 16 + q_;
        #pragma unroll
        for (int nt = 0; nt < 8; nt++) {
            int col = h * DH + nt * 8 + 2 * c_;
            *(__half2*)&ctx[(size_t)gr * HID + col] =
                __floats2half2_rn(o[mt][nt][0] * inv0, o[mt][nt][1] * inv0);
            *(__half2*)&ctx[(size_t)(gr + 8) * HID + col] =
                __floats2half2_rn(o[mt][nt][2] * inv1, o[mt][nt][3] * inv1);
        }
    }
    #undef AFILL
}

// ---------------------------------------------------------------------------
extern "C" void kernel_launch(void* const* d_in, const int* in_sizes, int n_in,
                              void* d_out, int out_size)
{
    const float* hs   = (const float*)d_in[0];
    const float* mask = (const float*)d_in[1];
    const float* Wq   = (const float*)d_in[2];
    const float* bq   = (const float*)d_in[3];
    const float* Wk   = (const float*)d_in[4];
    const float* bk   = (const float*)d_in[5];
    const float* Wv   = (const float*)d_in[6];
    const float* bv   = (const float*)d_in[7];
    const float* Wo   = (const float*)d_in[8];
    const float* bo   = (const float*)d_in[9];
    float* out = (float*)d_out;

    __half *hsr, *wt, *qh, *kh, *vht, *cb;
    int* mfl;
    cudaGetSymbolAddress((void**)&hsr, g_hsr);
    cudaGetSymbolAddress((void**)&wt,  g_wt);
    cudaGetSymbolAddress((void**)&qh,  g_qh);
    cudaGetSymbolAddress((void**)&kh,  g_kh);
    cudaGetSymbolAddress((void**)&vht, g_vht);
    cudaGetSymbolAddress((void**)&cb,  g_ctx);
    cudaGetSymbolAddress((void**)&mfl, g_mflag);

    cudaFuncSetAttribute(gemm10_qkv, cudaFuncAttributeMaxDynamicSharedMemorySize, G_SMEM_BYTES);
    cudaFuncSetAttribute(gemm10_o,   cudaFuncAttributeMaxDynamicSharedMemorySize, G_SMEM_BYTES);
    cudaFuncSetAttribute(attn8,      cudaFuncAttributeMaxDynamicSharedMemorySize, A_SMEM_BYTES);

    // --- pre-process: hs -> fp16; W -> transposed fp16; mask flags ---
    round_hs_h<<<(MTOT * HID / 4 + 255) / 256, 256>>>(hs, hsr, MTOT * HID / 4);
    dim3 tgrid(HID / 32, HID / 32, 4);
    transpose_w_h<<<tgrid, dim3(32, 8)>>>(Wq, Wk, Wv, Wo, wt);
    mask_flags<<<BATCH, 256>>>(mask, mfl);

    // --- fused QKV projections (Q pre-scaled by SCALE2) ---
    dim3 qkvgrid(HID / 128, MTOT / 128, 3);   // (6, 64, 3)
    gemm10_qkv<<<qkvgrid, 256, G_SMEM_BYTES>>>(hsr, wt, bq, bk, bv, qh, kh, vht);

    // --- attention ---
    dim3 agrid(SEQ / 128, NH, BATCH);    // (16, 12, 4) = 768 blocks
    attn8<<<agrid, 128, A_SMEM_BYTES>>>(qh, kh, vht, mask, mfl, cb);

    // --- output projection + GELU ---
    dim3 ggrid(HID / 128, MTOT / 128);   // (6, 64)
    gemm10_o<<<ggrid, 256, G_SMEM_BYTES>>>(cb, wt + 3 * (size_t)HID * HID, bo, out);
}

// round 16
// speedup vs baseline: 2.2800x; 1.0114x over previous
#include <cuda_runtime.h>
#include <cuda_fp16.h>
#include <math.h>
#include <stdint.h>

#define HID   768
#define NH    12
#define DH    64
#define BATCH 4
#define SEQ   2048
#define MTOT  (BATCH*SEQ)   // 8192

#define SCALE2 (0.125f * 1.44269504f)   // 1/sqrt(64) * log2(e), folded into Q
#define PEN2   (1e9f * 1.44269504f)

// Scratch (allocation-free rule: __device__ globals)
__device__ __half g_hsr[MTOT*HID];       // hs rounded to fp16
__device__ __half g_wt[4][HID*HID];      // W^T fp16: wt[n*HID+k] = (half)W[k*HID+n]
__device__ __half g_qh[MTOT*HID];        // q head-major fp16, pre-scaled by SCALE2
__device__ __half g_kh[MTOT*HID];        // k head-major fp16 [bh][s][d]
__device__ __half g_vht[MTOT*HID];       // v head-major TRANSPOSED fp16 [bh][d][s]
__device__ __half g_ctx[MTOT*HID];       // ctx standard layout fp16
__device__ int    g_mflag[BATCH];        // 1 if mask[b,:] is all ones

// ---------------------------------------------------------------------------
__device__ __forceinline__ float fexp2(float x) {
    float y;
    asm("ex2.approx.f32 %0, %1;" : "=f"(y) : "f"(x));
    return y;
}
__device__ __forceinline__ uint32_t h2exp2(uint32_t x) {
    uint32_t y;
    asm("ex2.approx.f16x2 %0, %1;" : "=r"(y) : "r"(x));
    return y;
}
__device__ __forceinline__ uint32_t packh2(float a, float b) {
    __half2 h = __floats2half2_rn(a, b);
    return *reinterpret_cast<uint32_t*>(&h);
}
__device__ __forceinline__ float2 h2f2(uint32_t x) {
    return __half22float2(*reinterpret_cast<__half2*>(&x));
}

__device__ __forceinline__ void mma_f16(float c[4],
    uint32_t a0, uint32_t a1, uint32_t a2, uint32_t a3,
    uint32_t b0, uint32_t b1)
{
    asm volatile(
        "mma.sync.aligned.m16n8k16.row.col.f32.f16.f16.f32 "
        "{%0,%1,%2,%3}, {%4,%5,%6,%7}, {%8,%9}, {%0,%1,%2,%3};"
        : "+f"(c[0]), "+f"(c[1]), "+f"(c[2]), "+f"(c[3])
        : "r"(a0), "r"(a1), "r"(a2), "r"(a3), "r"(b0), "r"(b1));
}
__device__ __forceinline__ void mma_f16c16(uint32_t c[2],
    uint32_t a0, uint32_t a1, uint32_t a2, uint32_t a3,
    uint32_t b0, uint32_t b1)
{
    asm volatile(
        "mma.sync.aligned.m16n8k16.row.col.f16.f16.f16.f16 "
        "{%0,%1}, {%2,%3,%4,%5}, {%6,%7}, {%0,%1};"
        : "+r"(c[0]), "+r"(c[1])
        : "r"(a0), "r"(a1), "r"(a2), "r"(a3), "r"(b0), "r"(b1));
}
__device__ __forceinline__ void ldsm_x4(uint32_t r[4], uint32_t addr)
{
    asm volatile(
        "ldmatrix.sync.aligned.m8n8.x4.shared.b16 {%0,%1,%2,%3}, [%4];"
        : "=r"(r[0]), "=r"(r[1]), "=r"(r[2]), "=r"(r[3]) : "r"(addr));
}

__device__ __forceinline__ uint32_t smaddr(const void* p) {
    return (uint32_t)__cvta_generic_to_shared(p);
}
__device__ __forceinline__ void cpa16(uint32_t dst, const void* src) {
    asm volatile("cp.async.cg.shared.global [%0], [%1], 16;" :: "r"(dst), "l"(src));
}
__device__ __forceinline__ void cpa_commit() {
    asm volatile("cp.async.commit_group;" ::: "memory");
}
__device__ __forceinline__ void cpa_wait1() {
    asm volatile("cp.async.wait_group 1;" ::: "memory");
}

// ---------------------------------------------------------------------------
// Pre-processing
// ---------------------------------------------------------------------------
__global__ void round_hs_h(const float* __restrict__ in, __half* __restrict__ out, int n4)
{
    int i = blockIdx.x * blockDim.x + threadIdx.x;
    if (i < n4) {
        float4 v = ((const float4*)in)[i];
        ((uint2*)out)[i] = make_uint2(packh2(v.x, v.y), packh2(v.z, v.w));
    }
}
__global__ void transpose_w_h(const float* __restrict__ w0, const float* __restrict__ w1,
                              const float* __restrict__ w2, const float* __restrict__ w3,
                              __half* __restrict__ out)
{
    __shared__ float tile[32][33];
    const int wi = blockIdx.z;
    const float* src = wi == 0 ? w0 : (wi == 1 ? w1 : (wi == 2 ? w2 : w3));
    __half* dst = out + (size_t)wi * HID * HID;
    const int kb = blockIdx.y * 32, nb = blockIdx.x * 32;
    #pragma unroll
    for (int i = threadIdx.y; i < 32; i += 8)
        tile[i][threadIdx.x] = src[(size_t)(kb + i) * HID + nb + threadIdx.x];
    __syncthreads();
    #pragma unroll
    for (int i = threadIdx.y; i < 32; i += 8)
        dst[(size_t)(nb + i) * HID + kb + threadIdx.x] = __float2half_rn(tile[threadIdx.x][i]);
}
__global__ void mask_flags(const float* __restrict__ mask, int* __restrict__ flags)
{
    const int b = blockIdx.x;
    int ok = 1;
    for (int i = threadIdx.x; i < SEQ; i += blockDim.x)
        ok &= (mask[b * SEQ + i] == 1.0f);
    ok = __syncthreads_and(ok);
    if (threadIdx.x == 0) flags[b] = ok;
}

// ---------------------------------------------------------------------------
// fp16 GEMM, 3-stage single-barrier pipeline (fill 1 ahead), ldmatrix frags.
// BM=128, BN=128, BK=64. 256 thr / 8 warps (4m x 2n), warp tile 32x64.
// Smem: 3 x (A[128][72h] + B[128][72h]) = 110592 B, 2 CTA/SM.
// Loop order: fill(t+1) -> commit -> wait1 -> BAR -> compute(t).
// Fill target (t+1)%3 was computed at t-2; the iter t-1 barrier certifies it.
// ---------------------------------------------------------------------------
#define H_TS (128*72)
#define G_SMEM_BYTES (6*H_TS*2)       // 110592

__device__ __forceinline__ void gemm_body(
    const __half* __restrict__ A, const __half* __restrict__ Wt,
    const float* __restrict__ bias, float* __restrict__ Cf,
    __half* __restrict__ Ch, int mode, float oscale)
{
    extern __shared__ __half sh[];
    __half* Asm = sh;                // [3][128][72]
    __half* Bsm = sh + 3 * H_TS;     // [3][128][72]

    const int tid  = threadIdx.x;
    const int lane = tid & 31;
    const int warp = tid >> 5;
    const int wm   = (warp >> 1) * 32;
    const int wn   = (warp & 1) * 64;
    const int m0   = blockIdx.y * 128;
    const int n0   = blockIdx.x * 128;
    const int c_   = lane & 3;
    const int q_   = lane >> 2;

    const int lrow = lane & 15;
    const int lkoh = ((lane >> 4) & 1) * 8;
    const uint32_t a_lane_off = (uint32_t)(((wm + lrow) * 72 + lkoh) * 2);
    const uint32_t b_lane_off = (uint32_t)(((wn + lrow) * 72 + lkoh) * 2);

    float acc[2][8][4] = {};
    const int nT = HID / 64;   // 12

    #define GFILL(buf, k0_) do {                                              \
        const int _k0 = (k0_);                                                \
        __half* Ad = Asm + (buf) * H_TS;                                      \
        __half* Bd = Bsm + (buf) * H_TS;                                      \
        _Pragma("unroll")                                                     \
        for (int i = 0; i < 4; i++) {                                         \
            int idx = tid + i * 256;                                          \
            int row = idx >> 3, ch = idx & 7;                                 \
            cpa16(smaddr(Ad + row * 72 + ch * 8),                             \
                  A + (size_t)(m0 + row) * HID + _k0 + ch * 8);               \
            cpa16(smaddr(Bd + row * 72 + ch * 8),                             \
                  Wt + (size_t)(n0 + row) * HID + _k0 + ch * 8);              \
        }                                                                     \
    } while (0)

    GFILL(0, 0);
    cpa_commit();

    for (int t = 0; t < nT; t++) {
        const int stage = t % 3;
        if (t + 1 < nT) { GFILL((t + 1) % 3, (t + 1) * 64); }
        cpa_commit();
        cpa_wait1();                 // own stage-t copies retired
        __syncthreads();             // publish all threads' stage-t data;
                                     // also gates next iter's fill target
        const uint32_t abase = smaddr(Asm + stage * H_TS) + a_lane_off;
        const uint32_t bbase = smaddr(Bsm + stage * H_TS) + b_lane_off;
        #pragma unroll
        for (int ksi = 0; ksi < 4; ksi++) {
            uint32_t a[2][4];
            ldsm_x4(a[0], abase + ksi * 32);
            ldsm_x4(a[1], abase + 16 * 144 + ksi * 32);
            #pragma unroll
            for (int ntp = 0; ntp < 4; ntp++) {
                uint32_t bf[4];
                ldsm_x4(bf, bbase + ntp * 16 * 144 + ksi * 32);
                mma_f16(acc[0][2*ntp],   a[0][0], a[0][1], a[0][2], a[0][3], bf[0], bf[2]);
                mma_f16(acc[0][2*ntp+1], a[0][0], a[0][1], a[0][2], a[0][3], bf[1], bf[3]);
                mma_f16(acc[1][2*ntp],   a[1][0], a[1][1], a[1][2], a[1][3], bf[0], bf[2]);
                mma_f16(acc[1][2*ntp+1], a[1][0], a[1][1], a[1][2], a[1][3], bf[1], bf[3]);
            }
        }
    }

    #pragma unroll
    for (int mt = 0; mt < 2; mt++) {
        int r0 = m0 + wm + mt * 16 + q_;
        int bb = r0 >> 11, s0 = r0 & 2047;
        #pragma unroll
        for (int nt = 0; nt < 8; nt++) {
            int col = n0 + wn + nt * 8 + 2 * c_;
            float bv0 = bias[col], bv1 = bias[col + 1];
            float v0 = acc[mt][nt][0] + bv0;
            float v1 = acc[mt][nt][1] + bv1;
            float v2 = acc[mt][nt][2] + bv0;
            float v3 = acc[mt][nt][3] + bv1;
            if (mode == 0) {
                v0 *= normcdff(v0); v1 *= normcdff(v1);
                v2 *= normcdff(v2); v3 *= normcdff(v3);
                *(float2*)&Cf[(size_t)r0       * HID + col] = make_float2(v0, v1);
                *(float2*)&Cf[(size_t)(r0 + 8) * HID + col] = make_float2(v2, v3);
            } else {
                int hh = col >> 6, d = col & 63;
                if (mode == 1) {
                    v0 *= oscale; v1 *= oscale; v2 *= oscale; v3 *= oscale;
                    __half* base = Ch + ((size_t)(bb * NH + hh) * SEQ) * 64;
                    *(__half2*)(base + (size_t)s0 * 64 + d)       = __floats2half2_rn(v0, v1);
                    *(__half2*)(base + (size_t)(s0 + 8) * 64 + d) = __floats2half2_rn(v2, v3);
                } else {
                    __half* base = Ch + ((size_t)(bb * NH + hh) * 64) * SEQ;
                    base[(size_t)d       * SEQ + s0]     = __float2half_rn(v0);
                    base[(size_t)(d + 1) * SEQ + s0]     = __float2half_rn(v1);
                    base[(size_t)d       * SEQ + s0 + 8] = __float2half_rn(v2);
                    base[(size_t)(d + 1) * SEQ + s0 + 8] = __float2half_rn(v3);
                }
            }
        }
    }
    #undef GFILL
}

__global__ __launch_bounds__(256, 2) void gemm12_qkv(
    const __half* __restrict__ A, const __half* __restrict__ Wt,
    const float* __restrict__ b0, const float* __restrict__ b1, const float* __restrict__ b2,
    __half* __restrict__ qh, __half* __restrict__ kh, __half* __restrict__ vht)
{
    const int z = blockIdx.z;
    const __half* W = Wt + (size_t)z * HID * HID;
    const float* bb = z == 0 ? b0 : (z == 1 ? b1 : b2);
    __half* Ch = z == 0 ? qh : (z == 1 ? kh : vht);
    gemm_body(A, W, bb, nullptr, Ch, z == 2 ? 2 : 1, z == 0 ? SCALE2 : 1.0f);
}

__global__ __launch_bounds__(256, 2) void gemm12_o(
    const __half* __restrict__ A, const __half* __restrict__ Wt,
    const float* __restrict__ bias, float* __restrict__ C)
{
    gemm_body(A, Wt, bias, C, nullptr, 0, 1.0f);
}

// ---------------------------------------------------------------------------
// Flash attention: fp16 QK (f16 accumulators), zero P packing, f16x2 exp,
// all-ones-mask fast path. 3-stage single-barrier pipeline (fill 1 ahead).
// Block = (b, h, 128-q-tile), 128 thr / 4 warps, 2 CTA/SM.
// Smem: 3 x (K[128][72h] + V[64][136h] + ms[128]f) = 109056 B.
// ---------------------------------------------------------------------------
#define TSK 128
#define K_ROWB 144
#define V_ROWB 272
#define KBUF_B (128*K_ROWB)
#define VBUF_B (64*V_ROWB)
#define AV_OFF (3*KBUF_B)
#define AM_OFF (AV_OFF + 3*VBUF_B)
#define A_SMEM_BYTES (AM_OFF + 3*TSK*4)   // 109056

__global__ __launch_bounds__(128, 2) void attn10(
    const __half* __restrict__ qh, const __half* __restrict__ kh,
    const __half* __restrict__ vht, const float* __restrict__ mask,
    const int* __restrict__ mflag, __half* __restrict__ ctx)
{
    extern __shared__ char smc[];
    float* msb = (float*)(smc + AM_OFF);

    const int tid  = threadIdx.x;
    const int lane = tid & 31;
    const int warp = tid >> 5;
    const int c_   = lane & 3;
    const int q_   = lane >> 2;
    const int b    = blockIdx.z;
    const int h    = blockIdx.y;
    const int q0   = blockIdx.x * 128;
    const int bS   = b * SEQ;
    const int bh   = b * NH + h;
    const int wq   = warp * 32;

    const bool fast = (mflag[b] != 0);

    const __half* kbase = kh  + (size_t)bh * SEQ * 64;
    const __half* vbase = vht + (size_t)bh * 64 * SEQ;

    #define AFILL(buf, k0_) do {                                               \
        const int _k0 = (k0_);                                                 \
        char* Kd = smc + (buf) * KBUF_B;                                       \
        char* Vd = smc + AV_OFF + (buf) * VBUF_B;                              \
        _Pragma("unroll")                                                      \
        for (int i = 0; i < 8; i++) {                                          \
            int idx = tid + i * 128;                                           \
            int kr = idx >> 3, ch = idx & 7;                                   \
            cpa16(smaddr(Kd + kr * K_ROWB + ch * 16),                          \
                  kbase + ((size_t)(_k0 + kr)) * 64 + ch * 8);                 \
            int vr = idx >> 4, vch = idx & 15;                                 \
            cpa16(smaddr(Vd + vr * V_ROWB + vch * 16),                         \
                  vbase + (size_t)vr * SEQ + _k0 + vch * 8);                   \
        }                                                                      \
        if (tid < 32) cpa16(smaddr((char*)(msb + (buf) * TSK) + tid * 16),     \
                            mask + bS + _k0 + tid * 4);                        \
    } while (0)

    AFILL(0, 0);
    cpa_commit();

    uint32_t qa[2][4][4];
    #pragma unroll
    for (int mt = 0; mt < 2; mt++) {
        const __half* p0 = qh + ((size_t)bh * SEQ + q0 + wq + mt * 16 + q_) * 64;
        const __half* p1 = p0 + 8 * 64;
        #pragma unroll
        for (int ksi = 0; ksi < 4; ksi++) {
            qa[mt][ksi][0] = *(const uint32_t*)(p0 + 16 * ksi + 2 * c_);
            qa[mt][ksi][1] = *(const uint32_t*)(p1 + 16 * ksi + 2 * c_);
            qa[mt][ksi][2] = *(const uint32_t*)(p0 + 16 * ksi + 2 * c_ + 8);
            qa[mt][ksi][3] = *(const uint32_t*)(p1 + 16 * ksi + 2 * c_ + 8);
        }
    }

    float mq[2][2];
    #pragma unroll
    for (int mt = 0; mt < 2; mt++) {
        mq[mt][0] = mask[bS + q0 + wq + mt * 16 + q_];
        mq[mt][1] = mask[bS + q0 + wq + mt * 16 + q_ + 8];
    }

    float l[2][2] = {};
    float o[2][8][4] = {};

    const int nT = SEQ / TSK;   // 16
    for (int t = 0; t < nT; t++) {
        const int stage = t % 3;
        if (t + 1 < nT) { AFILL((t + 1) % 3, (t + 1) * TSK); }
        cpa_commit();
        cpa_wait1();
        __syncthreads();

        const uint32_t* Kw = (const uint32_t*)(smc + stage * KBUF_B);
        const uint32_t* Vw = (const uint32_t*)(smc + AV_OFF + stage * VBUF_B);
        const float* mc = msb + stage * TSK;

        #pragma unroll
        for (int sub = 0; sub < 2; sub++) {
            // ---- S' = (Q*scale) K^T, f16 accumulators
            uint32_t sP[2][8][2] = {};
            #pragma unroll
            for (int ksi = 0; ksi < 4; ksi++) {
                #pragma unroll
                for (int nt = 0; nt < 8; nt++) {
                    int kw = (sub * 64 + nt * 8 + q_) * 36 + ksi * 8 + c_;
                    uint32_t b0 = Kw[kw];
                    uint32_t b1 = Kw[kw + 4];
                    mma_f16c16(sP[0][nt], qa[0][ksi][0], qa[0][ksi][1], qa[0][ksi][2], qa[0][ksi][3], b0, b1);
                    mma_f16c16(sP[1][nt], qa[1][ksi][0], qa[1][ksi][1], qa[1][ksi][2], qa[1][ksi][3], b0, b1);
                }
            }

            // ---- exp (+ mask on slow path), row sums in fp32
            if (fast) {
                #pragma unroll
                for (int mt = 0; mt < 2; mt++) {
                    #pragma unroll
                    for (int nt = 0; nt < 8; nt++) {
                        sP[mt][nt][0] = h2exp2(sP[mt][nt][0]);
                        sP[mt][nt][1] = h2exp2(sP[mt][nt][1]);
                        float2 p0 = h2f2(sP[mt][nt][0]);
                        float2 p1 = h2f2(sP[mt][nt][1]);
                        l[mt][0] += p0.x + p0.y;
                        l[mt][1] += p1.x + p1.y;
                    }
                }
            } else {
                #pragma unroll
                for (int mt = 0; mt < 2; mt++) {
                    #pragma unroll
                    for (int nt = 0; nt < 8; nt++) {
                        float mk0 = mc[sub * 64 + nt * 8 + 2 * c_];
                        float mk1 = mc[sub * 64 + nt * 8 + 2 * c_ + 1];
                        float2 f0 = h2f2(sP[mt][nt][0]);
                        float2 f1 = h2f2(sP[mt][nt][1]);
                        float e;
                        e = mq[mt][0] * mk0; f0.x = fexp2(e * f0.x - (1.0f - e) * PEN2);
                        e = mq[mt][0] * mk1; f0.y = fexp2(e * f0.y - (1.0f - e) * PEN2);
                        e = mq[mt][1] * mk0; f1.x = fexp2(e * f1.x - (1.0f - e) * PEN2);
                        e = mq[mt][1] * mk1; f1.y = fexp2(e * f1.y - (1.0f - e) * PEN2);
                        l[mt][0] += f0.x + f0.y;
                        l[mt][1] += f1.x + f1.y;
                        sP[mt][nt][0] = packh2(f0.x, f0.y);
                        sP[mt][nt][1] = packh2(f1.x, f1.y);
                    }
                }
            }

            // ---- O += P V (C-regs ARE the A-fragments)
            #pragma unroll
            for (int ksi = 0; ksi < 4; ksi++) {
                #pragma unroll
                for (int nt = 0; nt < 8; nt++) {
                    int vw = (q_ + nt * 8) * 68 + sub * 32 + ksi * 8 + c_;
                    uint32_t b0 = Vw[vw];
                    uint32_t b1 = Vw[vw + 4];
                    mma_f16(o[0][nt], sP[0][2*ksi][0], sP[0][2*ksi][1],
                            sP[0][2*ksi+1][0], sP[0][2*ksi+1][1], b0, b1);
                    mma_f16(o[1][nt], sP[1][2*ksi][0], sP[1][2*ksi][1],
                            sP[1][2*ksi+1][0], sP[1][2*ksi+1][1], b0, b1);
                }
            }
        }
    }

    // ---- final row-sum reduction over 4-lane group, normalize, write
    #pragma unroll
    for (int mt = 0; mt < 2; mt++) {
        #pragma unroll
        for (int half = 0; half < 2; half++) {
            l[mt][half] += __shfl_xor_sync(0xffffffffu, l[mt][half], 1);
            l[mt][half] += __shfl_xor_sync(0xffffffffu, l[mt][half], 2);
        }
    }

    #pragma unroll
    for (int mt = 0; mt < 2; mt++) {
        float inv0 = 1.0f / l[mt][0], inv1 = 1.0f / l[mt][1];
        int gr = bS + q0 + wq + mt * 16 + q_;
        #pragma unroll
        for (int nt = 0; nt < 8; nt++) {
            int col = h * DH + nt * 8 + 2 * c_;
            *(__half2*)&ctx[(size_t)gr * HID + col] =
                __floats2half2_rn(o[mt][nt][0] * inv0, o[mt][nt][1] * inv0);
            *(__half2*)&ctx[(size_t)(gr + 8) * HID + col] =
                __floats2half2_rn(o[mt][nt][2] * inv1, o[mt][nt][3] * inv1);
        }
    }
    #undef AFILL
}

// ---------------------------------------------------------------------------
extern "C" void kernel_launch(void* const* d_in, const int* in_sizes, int n_in,
                              void* d_out, int out_size)
{
    const float* hs   = (const float*)d_in[0];
    const float* mask = (const float*)d_in[1];
    const float* Wq   = (const float*)d_in[2];
    const float* bq   = (const float*)d_in[3];
    const float* Wk   = (const float*)d_in[4];
    const float* bk   = (const float*)d_in[5];
    const float* Wv   = (const float*)d_in[6];
    const float* bv   = (const float*)d_in[7];
    const float* Wo   = (const float*)d_in[8];
    const float* bo   = (const float*)d_in[9];
    float* out = (float*)d_out;

    __half *hsr, *wt, *qh, *kh, *vht, *cb;
    int* mfl;
    cudaGetSymbolAddress((void**)&hsr, g_hsr);
    cudaGetSymbolAddress((void**)&wt,  g_wt);
    cudaGetSymbolAddress((void**)&qh,  g_qh);
    cudaGetSymbolAddress((void**)&kh,  g_kh);
    cudaGetSymbolAddress((void**)&vht, g_vht);
    cudaGetSymbolAddress((void**)&cb,  g_ctx);
    cudaGetSymbolAddress((void**)&mfl, g_mflag);

    cudaFuncSetAttribute(gemm12_qkv, cudaFuncAttributeMaxDynamicSharedMemorySize, G_SMEM_BYTES);
    cudaFuncSetAttribute(gemm12_o,   cudaFuncAttributeMaxDynamicSharedMemorySize, G_SMEM_BYTES);
    cudaFuncSetAttribute(attn10,     cudaFuncAttributeMaxDynamicSharedMemorySize, A_SMEM_BYTES);

    // --- pre-process: hs -> fp16; W -> transposed fp16; mask flags ---
    round_hs_h<<<(MTOT * HID / 4 + 255) / 256, 256>>>(hs, hsr, MTOT * HID / 4);
    dim3 tgrid(HID / 32, HID / 32, 4);
    transpose_w_h<<<tgrid, dim3(32, 8)>>>(Wq, Wk, Wv, Wo, wt);
    mask_flags<<<BATCH, 256>>>(mask, mfl);

    // --- fused QKV projections (Q pre-scaled by SCALE2) ---
    dim3 qkvgrid(HID / 128, MTOT / 128, 3);   // (6, 64, 3)
    gemm12_qkv<<<qkvgrid, 256, G_SMEM_BYTES>>>(hsr, wt, bq, bk, bv, qh, kh, vht);

    // --- attention ---
    dim3 agrid(SEQ / 128, NH, BATCH);    // (16, 12, 4) = 768 blocks
    attn10<<<agrid, 128, A_SMEM_BYTES>>>(qh, kh, vht, mask, mfl, cb);

    // --- output projection + GELU ---
    dim3 ggrid(HID / 128, MTOT / 128);   // (6, 64)
    gemm12_o<<<ggrid, 256, G_SMEM_BYTES>>>(cb, wt + 3 * (size_t)HID * HID, bo, out);
}

// round 17
// speedup vs baseline: 2.2975x; 1.0077x over previous
#include <cuda_runtime.h>
#include <cuda_fp16.h>
#include <math.h>
#include <stdint.h>

#define HID   768
#define NH    12
#define DH    64
#define BATCH 4
#define SEQ   2048
#define MTOT  (BATCH*SEQ)   // 8192

#define SCALE2 (0.125f * 1.44269504f)   // 1/sqrt(64) * log2(e), folded into Q
#define PEN2   (1e9f * 1.44269504f)
#define ONESH2 0x3C003C00u              // (1.0h, 1.0h)

// Scratch (allocation-free rule: __device__ globals)
__device__ __half g_hsr[MTOT*HID];       // hs rounded to fp16
__device__ __half g_wt[4][HID*HID];      // W^T fp16: wt[n*HID+k] = (half)W[k*HID+n]
__device__ __half g_qh[MTOT*HID];        // q head-major fp16, pre-scaled by SCALE2
__device__ __half g_kh[MTOT*HID];        // k head-major fp16 [bh][s][d]
__device__ __half g_vht[MTOT*HID];       // v head-major TRANSPOSED fp16 [bh][d][s]
__device__ __half g_ctx[MTOT*HID];       // ctx standard layout fp16
__device__ int    g_mflag[BATCH];        // 1 if mask[b,:] is all ones

// ---------------------------------------------------------------------------
__device__ __forceinline__ float fexp2(float x) {
    float y;
    asm("ex2.approx.f32 %0, %1;" : "=f"(y) : "f"(x));
    return y;
}
__device__ __forceinline__ uint32_t h2exp2(uint32_t x) {
    uint32_t y;
    asm("ex2.approx.f16x2 %0, %1;" : "=r"(y) : "r"(x));
    return y;
}
__device__ __forceinline__ uint32_t packh2(float a, float b) {
    __half2 h = __floats2half2_rn(a, b);
    return *reinterpret_cast<uint32_t*>(&h);
}
__device__ __forceinline__ float2 h2f2(uint32_t x) {
    return __half22float2(*reinterpret_cast<__half2*>(&x));
}

__device__ __forceinline__ void mma_f16(float c[4],
    uint32_t a0, uint32_t a1, uint32_t a2, uint32_t a3,
    uint32_t b0, uint32_t b1)
{
    asm volatile(
        "mma.sync.aligned.m16n8k16.row.col.f32.f16.f16.f32 "
        "{%0,%1,%2,%3}, {%4,%5,%6,%7}, {%8,%9}, {%0,%1,%2,%3};"
        : "+f"(c[0]), "+f"(c[1]), "+f"(c[2]), "+f"(c[3])
        : "r"(a0), "r"(a1), "r"(a2), "r"(a3), "r"(b0), "r"(b1));
}
__device__ __forceinline__ void mma_f16c16(uint32_t c[2],
    uint32_t a0, uint32_t a1, uint32_t a2, uint32_t a3,
    uint32_t b0, uint32_t b1)
{
    asm volatile(
        "mma.sync.aligned.m16n8k16.row.col.f16.f16.f16.f16 "
        "{%0,%1}, {%2,%3,%4,%5}, {%6,%7}, {%0,%1};"
        : "+r"(c[0]), "+r"(c[1])
        : "r"(a0), "r"(a1), "r"(a2), "r"(a3), "r"(b0), "r"(b1));
}
__device__ __forceinline__ void ldsm_x4(uint32_t r[4], uint32_t addr)
{
    asm volatile(
        "ldmatrix.sync.aligned.m8n8.x4.shared.b16 {%0,%1,%2,%3}, [%4];"
        : "=r"(r[0]), "=r"(r[1]), "=r"(r[2]), "=r"(r[3]) : "r"(addr));
}

__device__ __forceinline__ uint32_t smaddr(const void* p) {
    return (uint32_t)__cvta_generic_to_shared(p);
}
__device__ __forceinline__ void cpa16(uint32_t dst, const void* src) {
    asm volatile("cp.async.cg.shared.global [%0], [%1], 16;" :: "r"(dst), "l"(src));
}
__device__ __forceinline__ void cpa_commit() {
    asm volatile("cp.async.commit_group;" ::: "memory");
}
__device__ __forceinline__ void cpa_wait1() {
    asm volatile("cp.async.wait_group 1;" ::: "memory");
}

// ---------------------------------------------------------------------------
// Pre-processing
// ---------------------------------------------------------------------------
__global__ void round_hs_h(const float* __restrict__ in, __half* __restrict__ out, int n4)
{
    int i = blockIdx.x * blockDim.x + threadIdx.x;
    if (i < n4) {
        float4 v = ((const float4*)in)[i];
        ((uint2*)out)[i] = make_uint2(packh2(v.x, v.y), packh2(v.z, v.w));
    }
}
__global__ void transpose_w_h(const float* __restrict__ w0, const float* __restrict__ w1,
                              const float* __restrict__ w2, const float* __restrict__ w3,
                              __half* __restrict__ out)
{
    __shared__ float tile[32][33];
    const int wi = blockIdx.z;
    const float* src = wi == 0 ? w0 : (wi == 1 ? w1 : (wi == 2 ? w2 : w3));
    __half* dst = out + (size_t)wi * HID * HID;
    const int kb = blockIdx.y * 32, nb = blockIdx.x * 32;
    #pragma unroll
    for (int i = threadIdx.y; i < 32; i += 8)
        tile[i][threadIdx.x] = src[(size_t)(kb + i) * HID + nb + threadIdx.x];
    __syncthreads();
    #pragma unroll
    for (int i = threadIdx.y; i < 32; i += 8)
        dst[(size_t)(nb + i) * HID + kb + threadIdx.x] = __float2half_rn(tile[threadIdx.x][i]);
}
__global__ void mask_flags(const float* __restrict__ mask, int* __restrict__ flags)
{
    const int b = blockIdx.x;
    int ok = 1;
    for (int i = threadIdx.x; i < SEQ; i += blockDim.x)
        ok &= (mask[b * SEQ + i] == 1.0f);
    ok = __syncthreads_and(ok);
    if (threadIdx.x == 0) flags[b] = ok;
}

// ---------------------------------------------------------------------------
// fp16 GEMM, 3-stage single-barrier pipeline (fill 1 ahead), ldmatrix frags.
// BM=128, BN=128, BK=64. 256 thr / 8 warps (4m x 2n), warp tile 32x64.
// Smem: 3 x (A[128][72h] + B[128][72h]) = 110592 B, 2 CTA/SM.
// ---------------------------------------------------------------------------
#define H_TS (128*72)
#define G_SMEM_BYTES (6*H_TS*2)       // 110592

__device__ __forceinline__ void gemm_body(
    const __half* __restrict__ A, const __half* __restrict__ Wt,
    const float* __restrict__ bias, float* __restrict__ Cf,
    __half* __restrict__ Ch, int mode, float oscale)
{
    extern __shared__ __half sh[];
    __half* Asm = sh;                // [3][128][72]
    __half* Bsm = sh + 3 * H_TS;     // [3][128][72]

    const int tid  = threadIdx.x;
    const int lane = tid & 31;
    const int warp = tid >> 5;
    const int wm   = (warp >> 1) * 32;
    const int wn   = (warp & 1) * 64;
    const int m0   = blockIdx.y * 128;
    const int n0   = blockIdx.x * 128;
    const int c_   = lane & 3;
    const int q_   = lane >> 2;

    const int lrow = lane & 15;
    const int lkoh = ((lane >> 4) & 1) * 8;
    const uint32_t a_lane_off = (uint32_t)(((wm + lrow) * 72 + lkoh) * 2);
    const uint32_t b_lane_off = (uint32_t)(((wn + lrow) * 72 + lkoh) * 2);

    float acc[2][8][4] = {};
    const int nT = HID / 64;   // 12

    #define GFILL(buf, k0_) do {                                              \
        const int _k0 = (k0_);                                                \
        __half* Ad = Asm + (buf) * H_TS;                                      \
        __half* Bd = Bsm + (buf) * H_TS;                                      \
        _Pragma("unroll")                                                     \
        for (int i = 0; i < 4; i++) {                                         \
            int idx = tid + i * 256;                                          \
            int row = idx >> 3, ch = idx & 7;                                 \
            cpa16(smaddr(Ad + row * 72 + ch * 8),                             \
                  A + (size_t)(m0 + row) * HID + _k0 + ch * 8);               \
            cpa16(smaddr(Bd + row * 72 + ch * 8),                             \
                  Wt + (size_t)(n0 + row) * HID + _k0 + ch * 8);              \
        }                                                                     \
    } while (0)

    GFILL(0, 0);
    cpa_commit();

    for (int t = 0; t < nT; t++) {
        const int stage = t % 3;
        if (t + 1 < nT) { GFILL((t + 1) % 3, (t + 1) * 64); }
        cpa_commit();
        cpa_wait1();
        __syncthreads();

        const uint32_t abase = smaddr(Asm + stage * H_TS) + a_lane_off;
        const uint32_t bbase = smaddr(Bsm + stage * H_TS) + b_lane_off;
        #pragma unroll
        for (int ksi = 0; ksi < 4; ksi++) {
            uint32_t a[2][4];
            ldsm_x4(a[0], abase + ksi * 32);
            ldsm_x4(a[1], abase + 16 * 144 + ksi * 32);
            #pragma unroll
            for (int ntp = 0; ntp < 4; ntp++) {
                uint32_t bf[4];
                ldsm_x4(bf, bbase + ntp * 16 * 144 + ksi * 32);
                mma_f16(acc[0][2*ntp],   a[0][0], a[0][1], a[0][2], a[0][3], bf[0], bf[2]);
                mma_f16(acc[0][2*ntp+1], a[0][0], a[0][1], a[0][2], a[0][3], bf[1], bf[3]);
                mma_f16(acc[1][2*ntp],   a[1][0], a[1][1], a[1][2], a[1][3], bf[0], bf[2]);
                mma_f16(acc[1][2*ntp+1], a[1][0], a[1][1], a[1][2], a[1][3], bf[1], bf[3]);
            }
        }
    }

    #pragma unroll
    for (int mt = 0; mt < 2; mt++) {
        int r0 = m0 + wm + mt * 16 + q_;
        int bb = r0 >> 11, s0 = r0 & 2047;
        #pragma unroll
        for (int nt = 0; nt < 8; nt++) {
            int col = n0 + wn + nt * 8 + 2 * c_;
            float bv0 = bias[col], bv1 = bias[col + 1];
            float v0 = acc[mt][nt][0] + bv0;
            float v1 = acc[mt][nt][1] + bv1;
            float v2 = acc[mt][nt][2] + bv0;
            float v3 = acc[mt][nt][3] + bv1;
            if (mode == 0) {
                v0 *= normcdff(v0); v1 *= normcdff(v1);
                v2 *= normcdff(v2); v3 *= normcdff(v3);
                *(float2*)&Cf[(size_t)r0       * HID + col] = make_float2(v0, v1);
                *(float2*)&Cf[(size_t)(r0 + 8) * HID + col] = make_float2(v2, v3);
            } else {
                int hh = col >> 6, d = col & 63;
                if (mode == 1) {
                    v0 *= oscale; v1 *= oscale; v2 *= oscale; v3 *= oscale;
                    __half* base = Ch + ((size_t)(bb * NH + hh) * SEQ) * 64;
                    *(__half2*)(base + (size_t)s0 * 64 + d)       = __floats2half2_rn(v0, v1);
                    *(__half2*)(base + (size_t)(s0 + 8) * 64 + d) = __floats2half2_rn(v2, v3);
                } else {
                    __half* base = Ch + ((size_t)(bb * NH + hh) * 64) * SEQ;
                    base[(size_t)d       * SEQ + s0]     = __float2half_rn(v0);
                    base[(size_t)(d + 1) * SEQ + s0]     = __float2half_rn(v1);
                    base[(size_t)d       * SEQ + s0 + 8] = __float2half_rn(v2);
                    base[(size_t)(d + 1) * SEQ + s0 + 8] = __float2half_rn(v3);
                }
            }
        }
    }
    #undef GFILL
}

__global__ __launch_bounds__(256, 2) void gemm13_qkv(
    const __half* __restrict__ A, const __half* __restrict__ Wt,
    const float* __restrict__ b0, const float* __restrict__ b1, const float* __restrict__ b2,
    __half* __restrict__ qh, __half* __restrict__ kh, __half* __restrict__ vht)
{
    const int z = blockIdx.z;
    const __half* W = Wt + (size_t)z * HID * HID;
    const float* bb = z == 0 ? b0 : (z == 1 ? b1 : b2);
    __half* Ch = z == 0 ? qh : (z == 1 ? kh : vht);
    gemm_body(A, W, bb, nullptr, Ch, z == 2 ? 2 : 1, z == 0 ? SCALE2 : 1.0f);
}

__global__ __launch_bounds__(256, 2) void gemm13_o(
    const __half* __restrict__ A, const __half* __restrict__ Wt,
    const float* __restrict__ bias, float* __restrict__ C)
{
    gemm_body(A, Wt, bias, C, nullptr, 0, 1.0f);
}

// ---------------------------------------------------------------------------
// Flash attention: fp16 QK (f16 accumulators), zero P packing, f16x2 exp,
// all-ones-mask fast path, 3-stage single-barrier pipeline.
// NEW: row-sum l computed by the tensor core (l = P @ ones) — deletes the
// serial FADD/cvt chain per tile AND the final shuffle reduction.
// Block = (b, h, 128-q-tile), 128 thr / 4 warps, 2 CTA/SM.
// Smem: 3 x (K[128][72h] + V[64][136h] + ms[128]f) = 109056 B.
// ---------------------------------------------------------------------------
#define TSK 128
#define K_ROWB 144
#define V_ROWB 272
#define KBUF_B (128*K_ROWB)
#define VBUF_B (64*V_ROWB)
#define AV_OFF (3*KBUF_B)
#define AM_OFF (AV_OFF + 3*VBUF_B)
#define A_SMEM_BYTES (AM_OFF + 3*TSK*4)   // 109056

__global__ __launch_bounds__(128, 2) void attn11(
    const __half* __restrict__ qh, const __half* __restrict__ kh,
    const __half* __restrict__ vht, const float* __restrict__ mask,
    const int* __restrict__ mflag, __half* __restrict__ ctx)
{
    extern __shared__ char smc[];
    float* msb = (float*)(smc + AM_OFF);

    const int tid  = threadIdx.x;
    const int lane = tid & 31;
    const int warp = tid >> 5;
    const int c_   = lane & 3;
    const int q_   = lane >> 2;
    const int b    = blockIdx.z;
    const int h    = blockIdx.y;
    const int q0   = blockIdx.x * 128;
    const int bS   = b * SEQ;
    const int bh   = b * NH + h;
    const int wq   = warp * 32;

    const bool fast = (mflag[b] != 0);

    const __half* kbase = kh  + (size_t)bh * SEQ * 64;
    const __half* vbase = vht + (size_t)bh * 64 * SEQ;

    #define AFILL(buf, k0_) do {                                               \
        const int _k0 = (k0_);                                                 \
        char* Kd = smc + (buf) * KBUF_B;                                       \
        char* Vd = smc + AV_OFF + (buf) * VBUF_B;                              \
        _Pragma("unroll")                                                      \
        for (int i = 0; i < 8; i++) {                                          \
            int idx = tid + i * 128;                                           \
            int kr = idx >> 3, ch = idx & 7;                                   \
            cpa16(smaddr(Kd + kr * K_ROWB + ch * 16),                          \
                  kbase + ((size_t)(_k0 + kr)) * 64 + ch * 8);                 \
            int vr = idx >> 4, vch = idx & 15;                                 \
            cpa16(smaddr(Vd + vr * V_ROWB + vch * 16),                         \
                  vbase + (size_t)vr * SEQ + _k0 + vch * 8);                   \
        }                                                                      \
        if (tid < 32) cpa16(smaddr((char*)(msb + (buf) * TSK) + tid * 16),     \
                            mask + bS + _k0 + tid * 4);                        \
    } while (0)

    AFILL(0, 0);
    cpa_commit();

    uint32_t qa[2][4][4];
    #pragma unroll
    for (int mt = 0; mt < 2; mt++) {
        const __half* p0 = qh + ((size_t)bh * SEQ + q0 + wq + mt * 16 + q_) * 64;
        const __half* p1 = p0 + 8 * 64;
        #pragma unroll
        for (int ksi = 0; ksi < 4; ksi++) {
            qa[mt][ksi][0] = *(const uint32_t*)(p0 + 16 * ksi + 2 * c_);
            qa[mt][ksi][1] = *(const uint32_t*)(p1 + 16 * ksi + 2 * c_);
            qa[mt][ksi][2] = *(const uint32_t*)(p0 + 16 * ksi + 2 * c_ + 8);
            qa[mt][ksi][3] = *(const uint32_t*)(p1 + 16 * ksi + 2 * c_ + 8);
        }
    }

    float mq[2][2];
    #pragma unroll
    for (int mt = 0; mt < 2; mt++) {
        mq[mt][0] = mask[bS + q0 + wq + mt * 16 + q_];
        mq[mt][1] = mask[bS + q0 + wq + mt * 16 + q_ + 8];
    }

    float lacc[2][4] = {};    // l = P @ ones via mma; [mt][0]=row q_, [mt][2]=row q_+8
    float o[2][8][4] = {};

    const int nT = SEQ / TSK;   // 16
    for (int t = 0; t < nT; t++) {
        const int stage = t % 3;
        if (t + 1 < nT) { AFILL((t + 1) % 3, (t + 1) * TSK); }
        cpa_commit();
        cpa_wait1();
        __syncthreads();

        const uint32_t* Kw = (const uint32_t*)(smc + stage * KBUF_B);
        const uint32_t* Vw = (const uint32_t*)(smc + AV_OFF + stage * VBUF_B);
        const float* mc = msb + stage * TSK;

        #pragma unroll
        for (int sub = 0; sub < 2; sub++) {
            // ---- S' = (Q*scale) K^T, f16 accumulators
            uint32_t sP[2][8][2] = {};
            #pragma unroll
            for (int ksi = 0; ksi < 4; ksi++) {
                #pragma unroll
                for (int nt = 0; nt < 8; nt++) {
                    int kw = (sub * 64 + nt * 8 + q_) * 36 + ksi * 8 + c_;
                    uint32_t b0 = Kw[kw];
                    uint32_t b1 = Kw[kw + 4];
                    mma_f16c16(sP[0][nt], qa[0][ksi][0], qa[0][ksi][1], qa[0][ksi][2], qa[0][ksi][3], b0, b1);
                    mma_f16c16(sP[1][nt], qa[1][ksi][0], qa[1][ksi][1], qa[1][ksi][2], qa[1][ksi][3], b0, b1);
                }
            }

            // ---- exp (+ mask on slow path); no scalar l accumulation
            if (fast) {
                #pragma unroll
                for (int mt = 0; mt < 2; mt++) {
                    #pragma unroll
                    for (int nt = 0; nt < 8; nt++) {
                        sP[mt][nt][0] = h2exp2(sP[mt][nt][0]);
                        sP[mt][nt][1] = h2exp2(sP[mt][nt][1]);
                    }
                }
            } else {
                #pragma unroll
                for (int mt = 0; mt < 2; mt++) {
                    #pragma unroll
                    for (int nt = 0; nt < 8; nt++) {
                        float mk0 = mc[sub * 64 + nt * 8 + 2 * c_];
                        float mk1 = mc[sub * 64 + nt * 8 + 2 * c_ + 1];
                        float2 f0 = h2f2(sP[mt][nt][0]);
                        float2 f1 = h2f2(sP[mt][nt][1]);
                        float e;
                        e = mq[mt][0] * mk0; f0.x = fexp2(e * f0.x - (1.0f - e) * PEN2);
                        e = mq[mt][0] * mk1; f0.y = fexp2(e * f0.y - (1.0f - e) * PEN2);
                        e = mq[mt][1] * mk0; f1.x = fexp2(e * f1.x - (1.0f - e) * PEN2);
                        e = mq[mt][1] * mk1; f1.y = fexp2(e * f1.y - (1.0f - e) * PEN2);
                        sP[mt][nt][0] = packh2(f0.x, f0.y);
                        sP[mt][nt][1] = packh2(f1.x, f1.y);
                    }
                }
            }

            // ---- O += P V; l += P @ ones (tensor core row sums)
            #pragma unroll
            for (int ksi = 0; ksi < 4; ksi++) {
                #pragma unroll
                for (int nt = 0; nt < 8; nt++) {
                    int vw = (q_ + nt * 8) * 68 + sub * 32 + ksi * 8 + c_;
                    uint32_t b0 = Vw[vw];
                    uint32_t b1 = Vw[vw + 4];
                    mma_f16(o[0][nt], sP[0][2*ksi][0], sP[0][2*ksi][1],
                            sP[0][2*ksi+1][0], sP[0][2*ksi+1][1], b0, b1);
                    mma_f16(o[1][nt], sP[1][2*ksi][0], sP[1][2*ksi][1],
                            sP[1][2*ksi+1][0], sP[1][2*ksi+1][1], b0, b1);
                }
                mma_f16(lacc[0], sP[0][2*ksi][0], sP[0][2*ksi][1],
                        sP[0][2*ksi+1][0], sP[0][2*ksi+1][1], ONESH2, ONESH2);
                mma_f16(lacc[1], sP[1][2*ksi][0], sP[1][2*ksi][1],
                        sP[1][2*ksi+1][0], sP[1][2*ksi+1][1], ONESH2, ONESH2);
            }
        }
    }

    // ---- normalize + write (row sums complete; no cross-lane reduction)
    #pragma unroll
    for (int mt = 0; mt < 2; mt++) {
        float inv0 = 1.0f / lacc[mt][0];
        float inv1 = 1.0f / lacc[mt][2];
        int gr = bS + q0 + wq + mt * 16 + q_;
        #pragma unroll
        for (int nt = 0; nt < 8; nt++) {
            int col = h * DH + nt * 8 + 2 * c_;
            *(__half2*)&ctx[(size_t)gr * HID + col] =
                __floats2half2_rn(o[mt][nt][0] * inv0, o[mt][nt][1] * inv0);
            *(__half2*)&ctx[(size_t)(gr + 8) * HID + col] =
                __floats2half2_rn(o[mt][nt][2] * inv1, o[mt][nt][3] * inv1);
        }
    }
    #undef AFILL
}

// ---------------------------------------------------------------------------
extern "C" void kernel_launch(void* const* d_in, const int* in_sizes, int n_in,
                              void* d_out, int out_size)
{
    const float* hs   = (const float*)d_in[0];
    const float* mask = (const float*)d_in[1];
    const float* Wq   = (const float*)d_in[2];
    const float* bq   = (const float*)d_in[3];
    const float* Wk   = (const float*)d_in[4];
    const float* bk   = (const float*)d_in[5];
    const float* Wv   = (const float*)d_in[6];
    const float* bv   = (const float*)d_in[7];
    const float* Wo   = (const float*)d_in[8];
    const float* bo   = (const float*)d_in[9];
    float* out = (float*)d_out;

    __half *hsr, *wt, *qh, *kh, *vht, *cb;
    int* mfl;
    cudaGetSymbolAddress((void**)&hsr, g_hsr);
    cudaGetSymbolAddress((void**)&wt,  g_wt);
    cudaGetSymbolAddress((void**)&qh,  g_qh);
    cudaGetSymbolAddress((void**)&kh,  g_kh);
    cudaGetSymbolAddress((void**)&vht, g_vht);
    cudaGetSymbolAddress((void**)&cb,  g_ctx);
    cudaGetSymbolAddress((void**)&mfl, g_mflag);

    cudaFuncSetAttribute(gemm13_qkv, cudaFuncAttributeMaxDynamicSharedMemorySize, G_SMEM_BYTES);
    cudaFuncSetAttribute(gemm13_o,   cudaFuncAttributeMaxDynamicSharedMemorySize, G_SMEM_BYTES);
    cudaFuncSetAttribute(attn11,     cudaFuncAttributeMaxDynamicSharedMemorySize, A_SMEM_BYTES);

    // --- pre-process: hs -> fp16; W -> transposed fp16; mask flags ---
    round_hs_h<<<(MTOT * HID / 4 + 255) / 256, 256>>>(hs, hsr, MTOT * HID / 4);
    dim3 tgrid(HID / 32, HID / 32, 4);
    transpose_w_h<<<tgrid, dim3(32, 8)>>>(Wq, Wk, Wv, Wo, wt);
    mask_flags<<<BATCH, 256>>>(mask, mfl);

    // --- fused QKV projections (Q pre-scaled by SCALE2) ---
    dim3 qkvgrid(HID / 128, MTOT / 128, 3);   // (6, 64, 3)
    gemm13_qkv<<<qkvgrid, 256, G_SMEM_BYTES>>>(hsr, wt, bq, bk, bv, qh, kh, vht);

    // --- attention ---
    dim3 agrid(SEQ / 128, NH, BATCH);    // (16, 12, 4) = 768 blocks
    attn11<<<agrid, 128, A_SMEM_BYTES>>>(qh, kh, vht, mask, mfl, cb);

    // --- output projection + GELU ---
    dim3 ggrid(HID / 128, MTOT / 128);   // (6, 64)
    gemm13_o<<<ggrid, 256, G_SMEM_BYTES>>>(cb, wt + 3 * (size_t)HID * HID, bo, out);
}